// round 6
// baseline (speedup 1.0000x reference)
#include <cuda_runtime.h>
#include <cuda_bf16.h>
#include <cstdint>

#define BB 8
#define SS 2048
#define DD 256
#define UU 128
#define MM (BB*SS)

// ---------------- device scratch (bf16 staging) ----------------
__device__ __nv_bfloat16 g_Xb[MM*DD];
__device__ __nv_bfloat16 g_Qb[MM*UU];
__device__ __nv_bfloat16 g_Kb[MM*UU];
__device__ __nv_bfloat16 g_Vb[MM*UU];
__device__ __nv_bfloat16 g_Ob[MM*UU];
__device__ __nv_bfloat16 g_Wq[DD*UU], g_Wk[DD*UU], g_Wv[DD*UU];
__device__ __nv_bfloat16 g_Wo[UU*DD];

// ---------------- helpers ----------------
__device__ __forceinline__ uint32_t smem_u32(const void* p){
    uint32_t a;
    asm("{ .reg .u64 t; cvta.to.shared.u64 t, %1; cvt.u32.u64 %0, t; }":"=r"(a):"l"(p));
    return a;
}
__device__ __forceinline__ float ex2f(float x){
    float r; asm("ex2.approx.ftz.f32 %0, %1;":"=f"(r):"f"(x)); return r;
}
__device__ __forceinline__ void mma_bf16(float* c, const uint32_t* a, const uint32_t* b){
    asm volatile("mma.sync.aligned.m16n8k16.row.col.f32.bf16.bf16.f32 "
        "{%0,%1,%2,%3}, {%4,%5,%6,%7}, {%8,%9}, {%0,%1,%2,%3};"
        : "+f"(c[0]),"+f"(c[1]),"+f"(c[2]),"+f"(c[3])
        : "r"(a[0]),"r"(a[1]),"r"(a[2]),"r"(a[3]), "r"(b[0]),"r"(b[1]));
}
__device__ __forceinline__ void ldsm_x4(uint32_t* r, uint32_t addr){
    asm volatile("ldmatrix.sync.aligned.m8n8.x4.shared.b16 {%0,%1,%2,%3}, [%4];"
        : "=r"(r[0]),"=r"(r[1]),"=r"(r[2]),"=r"(r[3]) : "r"(addr));
}
__device__ __forceinline__ void ldsm_x4_t(uint32_t* r, uint32_t addr){
    asm volatile("ldmatrix.sync.aligned.m8n8.x4.trans.shared.b16 {%0,%1,%2,%3}, [%4];"
        : "=r"(r[0]),"=r"(r[1]),"=r"(r[2]),"=r"(r[3]) : "r"(addr));
}
#define CP16(dst, src) asm volatile("cp.async.cg.shared.global [%0], [%1], 16;" :: "r"(dst), "l"(src) : "memory")
#define CP_COMMIT()    asm volatile("cp.async.commit_group;" ::: "memory")
#define CP_WAIT0()     asm volatile("cp.async.wait_group 0;" ::: "memory")
#define CP_WAIT1()     asm volatile("cp.async.wait_group 1;" ::: "memory")

// ===========================================================================
// Fused fp32 -> bf16 convert for X + all four weight matrices (one launch)
// ===========================================================================
#define NX4 (MM*DD/4)
#define NW4 (DD*UU/4)
__global__ void conv_all(const float* __restrict__ X,
                         const float* __restrict__ Wq, const float* __restrict__ Wk,
                         const float* __restrict__ Wv, const float* __restrict__ Wo,
                         __nv_bfloat16* __restrict__ xb,
                         __nv_bfloat16* __restrict__ wq, __nv_bfloat16* __restrict__ wk,
                         __nv_bfloat16* __restrict__ wv, __nv_bfloat16* __restrict__ wo)
{
    int i = blockIdx.x * blockDim.x + threadIdx.x;
    const float* src; __nv_bfloat16* dst; int j;
    if (i < NX4)              { src = X;  dst = xb; j = i; }
    else if (i < NX4 + NW4)   { src = Wq; dst = wq; j = i - NX4; }
    else if (i < NX4 + 2*NW4) { src = Wk; dst = wk; j = i - NX4 - NW4; }
    else if (i < NX4 + 3*NW4) { src = Wv; dst = wv; j = i - NX4 - 2*NW4; }
    else if (i < NX4 + 4*NW4) { src = Wo; dst = wo; j = i - NX4 - 3*NW4; }
    else return;
    float4 v = ((const float4*)src)[j];
    __nv_bfloat162 a = __floats2bfloat162_rn(v.x, v.y);
    __nv_bfloat162 b = __floats2bfloat162_rn(v.z, v.w);
    uint2 o; o.x = *(uint32_t*)&a; o.y = *(uint32_t*)&b;
    ((uint2*)dst)[j] = o;
}

// ===========================================================================
// QKV projection, X-resident: one CTA computes Q,K,V for its 128 rows.
// smem: X tile 128x256 bf16 (64KB, 512B rows) + W double buffer 2x16KB = 96KB
// Pipeline: 12 W chunks (z,kc), X as one big initial group.
// ===========================================================================
#define QKV_SMEM (65536 + 32768)
__global__ void __launch_bounds__(256, 1)
qkv_mma(const __nv_bfloat16* __restrict__ Xb,
        const __nv_bfloat16* __restrict__ Wqb, const __nv_bfloat16* __restrict__ Wkb,
        const __nv_bfloat16* __restrict__ Wvb,
        __nv_bfloat16* __restrict__ Qb, __nv_bfloat16* __restrict__ Kb,
        __nv_bfloat16* __restrict__ Vb)
{
    extern __shared__ __align__(128) char sm[];
    const uint32_t sb = smem_u32(sm);
    const int t = threadIdx.x, w = t >> 5, lane = t & 31, l7 = lane & 7;
    const int rowBase = blockIdx.x * 128;
    const char* Xg = (const char*)(Xb + (size_t)rowBase * DD);
    const __nv_bfloat16* Wg[3] = { Wqb, Wkb, Wvb };
    __nv_bfloat16* Og[3] = { Qb, Kb, Vb };

    // ---- X tile: 128 rows x 512B, swizzled chunks ----
#pragma unroll
    for (int q = 0; q < 16; q++){
        int idx = t + q*256;            // 0..4095
        int row = idx >> 5, ch = idx & 31;
        CP16(sb + row*512 + (uint32_t)((ch ^ (row & 7)) << 4),
             Xg + (size_t)row*512 + ch*16);
    }
    CP_COMMIT();

    auto load_w = [&](int i){           // chunk i: z = i>>2, kc = i&3
        const char* src = (const char*)Wg[i >> 2] + (size_t)(i & 3)*64*256;
        uint32_t wd = sb + 65536 + (uint32_t)(i & 1)*16384;
#pragma unroll
        for (int q = 0; q < 4; q++){
            int idx = t + q*256, row = idx >> 4, ch = idx & 15;
            CP16(wd + row*256 + (uint32_t)((ch ^ (row & 7)) << 4),
                 src + (size_t)row*256 + ch*16);
        }
        CP_COMMIT();
    };
    load_w(0);
    load_w(1);

    float acc[16][4];
    const int arow = 16*w + (lane & 15);
    const int r0 = rowBase + 16*w + (lane >> 2);

    for (int i = 0; i < 12; i++){
        if (i < 11) CP_WAIT1(); else CP_WAIT0();
        __syncthreads();
        const int kc = i & 3, z = i >> 2;
        if (kc == 0){
#pragma unroll
            for (int p = 0; p < 16; p++)
#pragma unroll
                for (int j = 0; j < 4; j++) acc[p][j] = 0.f;
        }
        const uint32_t wb = sb + 65536 + (uint32_t)(i & 1)*16384;
#pragma unroll
        for (int t4 = 0; t4 < 4; t4++){
            uint32_t a[4];
            int ach = kc*8 + 2*t4 + (lane >> 4);
            ldsm_x4(a, sb + arow*512 + (uint32_t)((ach ^ (arow & 7)) << 4));
            int krow = 16*t4 + l7 + ((lane >> 3) & 1)*8;
#pragma unroll
            for (int u2 = 0; u2 < 8; u2++){
                uint32_t bv[4];
                int ch = 2*u2 + (lane >> 4);
                ldsm_x4_t(bv, wb + krow*256 + (uint32_t)((ch ^ l7) << 4));
                mma_bf16(acc[2*u2],     a, bv);
                mma_bf16(acc[2*u2 + 1], a, bv + 2);
            }
        }
        if (kc == 3){
            __nv_bfloat16* Ob = Og[z];
#pragma unroll
            for (int nt = 0; nt < 16; nt++){
                int c0 = 8*nt + 2*(lane & 3);
                __nv_bfloat162 h0 = __floats2bfloat162_rn(acc[nt][0], acc[nt][1]);
                __nv_bfloat162 h1 = __floats2bfloat162_rn(acc[nt][2], acc[nt][3]);
                *(uint32_t*)(Ob + (size_t)r0*UU + c0)       = *(uint32_t*)&h0;
                *(uint32_t*)(Ob + (size_t)(r0 + 8)*UU + c0) = *(uint32_t*)&h1;
            }
        }
        __syncthreads();
        if (i < 10) load_w(i + 2);
    }
}

// ===========================================================================
// Output projection on mma.sync (occ 2)
// ===========================================================================
#define PROJ_SMEM 65536
__global__ void __launch_bounds__(256, 2)
proj_mma(const __nv_bfloat16* __restrict__ Ab, const __nv_bfloat16* __restrict__ Wob,
         float* __restrict__ C, const float* __restrict__ bias,
         const float* __restrict__ res)
{
    extern __shared__ __align__(128) char sm[];
    const uint32_t sb = smem_u32(sm);
    const int t = threadIdx.x, w = t >> 5, lane = t & 31, l7 = lane & 7;
    const int rowBase = blockIdx.y * 128, colBase = blockIdx.x * 128;

    const char* Ag = (const char*)(Ab + (size_t)rowBase * UU);
    const char* Wg = (const char*)Wob + (size_t)colBase * 2;
#pragma unroll
    for (int q = 0; q < 8; q++){
        int idx = t + q*256, row = idx >> 4, ch = idx & 15;
        uint32_t sw = (uint32_t)((ch ^ (row & 7)) << 4);
        CP16(sb + row*256 + sw,         Ag + (size_t)row*256 + ch*16);
        CP16(sb + 32768 + row*256 + sw, Wg + (size_t)row*512 + ch*16);
    }
    CP_COMMIT();
    CP_WAIT0();
    __syncthreads();

    float acc[16][4];
#pragma unroll
    for (int i = 0; i < 16; i++)
#pragma unroll
        for (int j = 0; j < 4; j++) acc[i][j] = 0.f;

#pragma unroll
    for (int t4 = 0; t4 < 8; t4++){
        uint32_t a[4];
        int arow = 16*w + (lane & 15);
        int ach  = 2*t4 + (lane >> 4);
        ldsm_x4(a, sb + arow*256 + (uint32_t)((ach ^ (arow & 7)) << 4));
        int krow = 16*t4 + l7 + ((lane >> 3) & 1)*8;
#pragma unroll
        for (int u2 = 0; u2 < 8; u2++){
            uint32_t bv[4];
            int ch = 2*u2 + (lane >> 4);
            ldsm_x4_t(bv, sb + 32768 + krow*256 + (uint32_t)((ch ^ l7) << 4));
            mma_bf16(acc[2*u2],     a, bv);
            mma_bf16(acc[2*u2 + 1], a, bv + 2);
        }
    }

    int r0 = rowBase + 16*w + (lane >> 2);
#pragma unroll
    for (int nt = 0; nt < 16; nt++){
        int c0 = colBase + 8*nt + 2*(lane & 3);
        float2 bi = *(const float2*)(bias + c0);
        float2 x0 = *(const float2*)(res + (size_t)r0*DD + c0);
        float2 x1 = *(const float2*)(res + (size_t)(r0 + 8)*DD + c0);
        *(float2*)(C + (size_t)r0*DD + c0) =
            make_float2(acc[nt][0] + bi.x + x0.x, acc[nt][1] + bi.y + x0.y);
        *(float2*)(C + (size_t)(r0 + 8)*DD + c0) =
            make_float2(acc[nt][2] + bi.x + x1.x, acc[nt][3] + bi.y + x1.y);
    }
}

// ===========================================================================
// Flash attention on warp-level bf16 mma.sync (occ 2 attempt)
// ===========================================================================
#define ATT_SMEM 65536

__device__ __forceinline__ void load_kv(uint32_t dst, const char* Kg, const char* Vg,
                                        int tile, int t){
    const char* ks = Kg + (size_t)tile * 64 * 256;
    const char* vs = Vg + (size_t)tile * 64 * 256;
#pragma unroll
    for (int q = 0; q < 4; q++){
        int idx = t + q*256;
        int row = idx >> 4, ch = idx & 15;
        uint32_t d = dst + row*256 + (uint32_t)((ch ^ (row & 7)) << 4);
        CP16(d,         ks + (size_t)row*256 + ch*16);
        CP16(d + 16384, vs + (size_t)row*256 + ch*16);
    }
    CP_COMMIT();
}

__global__ void __launch_bounds__(256, 2)
attn_mma(const __nv_bfloat16* __restrict__ Q, const __nv_bfloat16* __restrict__ K,
         const __nv_bfloat16* __restrict__ V, __nv_bfloat16* __restrict__ O)
{
    extern __shared__ __align__(128) char sm[];
    const uint32_t sb = smem_u32(sm);
    const int t = threadIdx.x, w = t >> 5, lane = t & 31;
    const int b = blockIdx.y, qb = blockIdx.x;
    const int l7 = lane & 7;

    const char* Qg = (const char*)(Q + (size_t)(b*SS + qb*128)*UU);
#pragma unroll
    for (int q = 0; q < 8; q++){
        int idx = t + q*256;
        int row = idx >> 4, ch = idx & 15;
        CP16(sb + row*256 + (uint32_t)((ch ^ (row & 7)) << 4),
             Qg + (size_t)row*256 + ch*16);
    }
    CP_COMMIT();
    CP_WAIT0();
    __syncthreads();

    uint32_t qa[8][4];
    {
        int row = 16*w + (lane & 15);
        int rx  = row & 7;
        int cb  = (lane >> 4) & 1;
#pragma unroll
        for (int kt = 0; kt < 8; kt++){
            int chunk = 2*kt + cb;
            ldsm_x4(qa[kt], sb + row*256 + (uint32_t)((chunk ^ rx) << 4));
        }
    }
    __syncthreads();

    float oa[16][4];
#pragma unroll
    for (int i = 0; i < 16; i++)
#pragma unroll
        for (int j = 0; j < 4; j++) oa[i][j] = 0.f;
    float lsum0 = 0.f, lsum1 = 0.f;

    const char* Kg = (const char*)(K + (size_t)(b*SS)*UU);
    const char* Vg = (const char*)(V + (size_t)(b*SS)*UU);

    load_kv(sb,         Kg, Vg, 0, t);
    load_kv(sb + 32768, Kg, Vg, 1, t);

    const float C = 0.12751751699104088f;   // log2(e) / sqrt(128)

    for (int i = 0; i < 32; i++){
        if (i < 31) CP_WAIT1(); else CP_WAIT0();
        __syncthreads();
        const uint32_t kbuf = sb + (uint32_t)(i & 1)*32768;
        const uint32_t vbuf = kbuf + 16384;

#pragma unroll
        for (int tt = 0; tt < 4; tt++){
            float sa[2][4];
#pragma unroll
            for (int jj = 0; jj < 2; jj++){
                sa[jj][0]=sa[jj][1]=sa[jj][2]=sa[jj][3]=0.f;
                int row = 8*(2*tt + jj) + l7;
#pragma unroll
                for (int c = 0; c < 4; c++){
                    uint32_t bv[4];
                    int chunk = 4*c + (lane >> 3);
                    ldsm_x4(bv, kbuf + row*256 + (uint32_t)((chunk ^ l7) << 4));
                    mma_bf16(sa[jj], qa[2*c],   bv);
                    mma_bf16(sa[jj], qa[2*c+1], bv + 2);
                }
            }
            float e00 = ex2f(sa[0][0]*C), e01 = ex2f(sa[0][1]*C);
            float e02 = ex2f(sa[0][2]*C), e03 = ex2f(sa[0][3]*C);
            float e10 = ex2f(sa[1][0]*C), e11 = ex2f(sa[1][1]*C);
            float e12 = ex2f(sa[1][2]*C), e13 = ex2f(sa[1][3]*C);
            lsum0 += e00 + e01 + e10 + e11;
            lsum1 += e02 + e03 + e12 + e13;
            uint32_t pa[4];
            __nv_bfloat162 h;
            h = __floats2bfloat162_rn(e00, e01); pa[0] = *(uint32_t*)&h;
            h = __floats2bfloat162_rn(e02, e03); pa[1] = *(uint32_t*)&h;
            h = __floats2bfloat162_rn(e10, e11); pa[2] = *(uint32_t*)&h;
            h = __floats2bfloat162_rn(e12, e13); pa[3] = *(uint32_t*)&h;
            int vrow = 16*tt + l7 + ((lane >> 3) & 1) * 8;
#pragma unroll
            for (int u2 = 0; u2 < 8; u2++){
                uint32_t bv[4];
                int chunk = 2*u2 + (lane >> 4);
                ldsm_x4_t(bv, vbuf + vrow*256 + (uint32_t)((chunk ^ l7) << 4));
                mma_bf16(oa[2*u2],     pa, bv);
                mma_bf16(oa[2*u2 + 1], pa, bv + 2);
            }
        }
        if (i < 30){
            __syncthreads();
            load_kv(sb + (uint32_t)(i & 1)*32768, Kg, Vg, i + 2, t);
        }
    }

    lsum0 += __shfl_xor_sync(0xffffffffu, lsum0, 1);
    lsum0 += __shfl_xor_sync(0xffffffffu, lsum0, 2);
    lsum1 += __shfl_xor_sync(0xffffffffu, lsum1, 1);
    lsum1 += __shfl_xor_sync(0xffffffffu, lsum1, 2);
    float inv0 = 1.f / lsum0, inv1 = 1.f / lsum1;

    int r0 = 16*w + (lane >> 2);
    __nv_bfloat16* O0 = O + (size_t)(b*SS + qb*128 + r0)*UU + 2*(lane & 3);
#pragma unroll
    for (int nt = 0; nt < 16; nt++){
        __nv_bfloat162 h0 = __floats2bfloat162_rn(oa[nt][0]*inv0, oa[nt][1]*inv0);
        __nv_bfloat162 h1 = __floats2bfloat162_rn(oa[nt][2]*inv1, oa[nt][3]*inv1);
        *(uint32_t*)(O0 + nt*8)          = *(uint32_t*)&h0;
        *(uint32_t*)(O0 + 8*UU + nt*8)   = *(uint32_t*)&h1;
    }
}

// ===========================================================================
extern "C" void kernel_launch(void* const* d_in, const int* in_sizes, int n_in,
                              void* d_out, int out_size)
{
    const float* X   = (const float*)d_in[0];
    const float* W_q = (const float*)d_in[1];
    const float* W_k = (const float*)d_in[2];
    const float* W_v = (const float*)d_in[3];
    const float* W_o = (const float*)d_in[4];
    const float* b_o = (const float*)d_in[5];
    float* out = (float*)d_out;

    __nv_bfloat16 *xb, *qb, *kb, *vb, *ob, *wq, *wk, *wv, *wo;
    cudaGetSymbolAddress((void**)&xb, g_Xb);
    cudaGetSymbolAddress((void**)&qb, g_Qb);
    cudaGetSymbolAddress((void**)&kb, g_Kb);
    cudaGetSymbolAddress((void**)&vb, g_Vb);
    cudaGetSymbolAddress((void**)&ob, g_Ob);
    cudaGetSymbolAddress((void**)&wq, g_Wq);
    cudaGetSymbolAddress((void**)&wk, g_Wk);
    cudaGetSymbolAddress((void**)&wv, g_Wv);
    cudaGetSymbolAddress((void**)&wo, g_Wo);

    cudaFuncSetAttribute(qkv_mma,  cudaFuncAttributeMaxDynamicSharedMemorySize, QKV_SMEM);
    cudaFuncSetAttribute(attn_mma, cudaFuncAttributeMaxDynamicSharedMemorySize, ATT_SMEM);
    cudaFuncSetAttribute(proj_mma, cudaFuncAttributeMaxDynamicSharedMemorySize, PROJ_SMEM);

    conv_all<<<(NX4 + 4*NW4 + 255)/256, 256>>>(X, W_q, W_k, W_v, W_o,
                                               xb, wq, wk, wv, wo);
    qkv_mma<<<MM/128, 256, QKV_SMEM>>>(xb, wq, wk, wv, qb, kb, vb);
    attn_mma<<<dim3(SS/128, BB), 256, ATT_SMEM>>>(qb, kb, vb, ob);
    proj_mma<<<dim3(DD/128, MM/128), 256, PROJ_SMEM>>>(ob, wo, out, b_o, X);
}

// round 7
// speedup vs baseline: 1.1573x; 1.1573x over previous
#include <cuda_runtime.h>
#include <cuda_bf16.h>
#include <cstdint>

#define BB 8
#define SS 2048
#define DD 256
#define UU 128
#define MM (BB*SS)

// ---------------- device scratch (bf16 staging) ----------------
__device__ __nv_bfloat16 g_Xb[MM*DD];
__device__ __nv_bfloat16 g_Qb[MM*UU];
__device__ __nv_bfloat16 g_Kb[MM*UU];
__device__ __nv_bfloat16 g_Vb[MM*UU];
__device__ __nv_bfloat16 g_Ob[MM*UU];
__device__ __nv_bfloat16 g_Wq[DD*UU], g_Wk[DD*UU], g_Wv[DD*UU];
__device__ __nv_bfloat16 g_Wo[UU*DD];

// ---------------- helpers ----------------
__device__ __forceinline__ uint32_t smem_u32(const void* p){
    uint32_t a;
    asm("{ .reg .u64 t; cvta.to.shared.u64 t, %1; cvt.u32.u64 %0, t; }":"=r"(a):"l"(p));
    return a;
}
__device__ __forceinline__ float ex2f(float x){
    float r; asm("ex2.approx.ftz.f32 %0, %1;":"=f"(r):"f"(x)); return r;
}
__device__ __forceinline__ void mma_bf16(float* c, const uint32_t* a, const uint32_t* b){
    asm volatile("mma.sync.aligned.m16n8k16.row.col.f32.bf16.bf16.f32 "
        "{%0,%1,%2,%3}, {%4,%5,%6,%7}, {%8,%9}, {%0,%1,%2,%3};"
        : "+f"(c[0]),"+f"(c[1]),"+f"(c[2]),"+f"(c[3])
        : "r"(a[0]),"r"(a[1]),"r"(a[2]),"r"(a[3]), "r"(b[0]),"r"(b[1]));
}
__device__ __forceinline__ void ldsm_x4(uint32_t* r, uint32_t addr){
    asm volatile("ldmatrix.sync.aligned.m8n8.x4.shared.b16 {%0,%1,%2,%3}, [%4];"
        : "=r"(r[0]),"=r"(r[1]),"=r"(r[2]),"=r"(r[3]) : "r"(addr));
}
__device__ __forceinline__ void ldsm_x4_t(uint32_t* r, uint32_t addr){
    asm volatile("ldmatrix.sync.aligned.m8n8.x4.trans.shared.b16 {%0,%1,%2,%3}, [%4];"
        : "=r"(r[0]),"=r"(r[1]),"=r"(r[2]),"=r"(r[3]) : "r"(addr));
}
#define CP16(dst, src) asm volatile("cp.async.cg.shared.global [%0], [%1], 16;" :: "r"(dst), "l"(src) : "memory")
#define CP_COMMIT()    asm volatile("cp.async.commit_group;" ::: "memory")
#define CP_WAIT0()     asm volatile("cp.async.wait_group 0;" ::: "memory")
#define CP_WAIT1()     asm volatile("cp.async.wait_group 1;" ::: "memory")

// ===========================================================================
// Fused fp32 -> bf16 convert (one launch)
// ===========================================================================
#define NX4 (MM*DD/4)
#define NW4 (DD*UU/4)
__global__ void conv_all(const float* __restrict__ X,
                         const float* __restrict__ Wq, const float* __restrict__ Wk,
                         const float* __restrict__ Wv, const float* __restrict__ Wo,
                         __nv_bfloat16* __restrict__ xb,
                         __nv_bfloat16* __restrict__ wq, __nv_bfloat16* __restrict__ wk,
                         __nv_bfloat16* __restrict__ wv, __nv_bfloat16* __restrict__ wo)
{
    int i = blockIdx.x * blockDim.x + threadIdx.x;
    const float* src; __nv_bfloat16* dst; int j;
    if (i < NX4)              { src = X;  dst = xb; j = i; }
    else if (i < NX4 + NW4)   { src = Wq; dst = wq; j = i - NX4; }
    else if (i < NX4 + 2*NW4) { src = Wk; dst = wk; j = i - NX4 - NW4; }
    else if (i < NX4 + 3*NW4) { src = Wv; dst = wv; j = i - NX4 - 2*NW4; }
    else if (i < NX4 + 4*NW4) { src = Wo; dst = wo; j = i - NX4 - 3*NW4; }
    else return;
    float4 v = ((const float4*)src)[j];
    __nv_bfloat162 a = __floats2bfloat162_rn(v.x, v.y);
    __nv_bfloat162 b = __floats2bfloat162_rn(v.z, v.w);
    uint2 o; o.x = *(uint32_t*)&a; o.y = *(uint32_t*)&b;
    ((uint2*)dst)[j] = o;
}

// ===========================================================================
// QKV projection (round-5 version: grid (rows, z), double-buffered K chunks)
// ===========================================================================
#define QKV_SMEM 65536
__global__ void __launch_bounds__(256, 1)
qkv_mma(const __nv_bfloat16* __restrict__ Xb,
        const __nv_bfloat16* __restrict__ Wqb, const __nv_bfloat16* __restrict__ Wkb,
        const __nv_bfloat16* __restrict__ Wvb,
        __nv_bfloat16* __restrict__ Qb, __nv_bfloat16* __restrict__ Kb,
        __nv_bfloat16* __restrict__ Vb)
{
    extern __shared__ __align__(128) char sm[];
    const uint32_t sb = smem_u32(sm);
    const int t = threadIdx.x, w = t >> 5, lane = t & 31, l7 = lane & 7;
    const int z = blockIdx.y;
    const __nv_bfloat16* Wb = (z == 0) ? Wqb : (z == 1) ? Wkb : Wvb;
    __nv_bfloat16* Ob = (z == 0) ? Qb : (z == 1) ? Kb : Vb;
    const int rowBase = blockIdx.x * 128;
    const char* Xg = (const char*)(Xb + (size_t)rowBase * DD);
    const char* Wg = (const char*)Wb;

    auto load_chunk = [&](int kc, int buf){
        uint32_t xd = sb + (uint32_t)buf * 16384;           // X: 128 x 64 bf16
#pragma unroll
        for (int q = 0; q < 4; q++){
            int idx = t + q*256, row = idx >> 3, ch = idx & 7;
            CP16(xd + row*128 + (uint32_t)((ch ^ (row & 7)) << 4),
                 Xg + (size_t)row*512 + kc*128 + ch*16);
        }
        uint32_t wd = sb + 32768 + (uint32_t)buf * 16384;   // W: 64 x 128 bf16
#pragma unroll
        for (int q = 0; q < 4; q++){
            int idx = t + q*256, row = idx >> 4, ch = idx & 15;
            CP16(wd + row*256 + (uint32_t)((ch ^ (row & 7)) << 4),
                 Wg + (size_t)(kc*64 + row)*256 + ch*16);
        }
        CP_COMMIT();
    };

    float acc[16][4];
#pragma unroll
    for (int i = 0; i < 16; i++)
#pragma unroll
        for (int j = 0; j < 4; j++) acc[i][j] = 0.f;

    load_chunk(0, 0);
    load_chunk(1, 1);

    for (int kc = 0; kc < 4; kc++){
        if (kc < 3) CP_WAIT1(); else CP_WAIT0();
        __syncthreads();
        const uint32_t xb = sb + (uint32_t)(kc & 1)*16384;
        const uint32_t wb = sb + 32768 + (uint32_t)(kc & 1)*16384;
#pragma unroll
        for (int t4 = 0; t4 < 4; t4++){
            uint32_t a[4];
            int arow = 16*w + (lane & 15);
            int ach  = 2*t4 + (lane >> 4);
            ldsm_x4(a, xb + arow*128 + (uint32_t)((ach ^ (arow & 7)) << 4));
            int krow = 16*t4 + l7 + ((lane >> 3) & 1)*8;
#pragma unroll
            for (int u2 = 0; u2 < 8; u2++){
                uint32_t bv[4];
                int ch = 2*u2 + (lane >> 4);
                ldsm_x4_t(bv, wb + krow*256 + (uint32_t)((ch ^ l7) << 4));
                mma_bf16(acc[2*u2],     a, bv);
                mma_bf16(acc[2*u2 + 1], a, bv + 2);
            }
        }
        if (kc < 2){ __syncthreads(); load_chunk(kc + 2, kc & 1); }
    }

    int r0 = rowBase + 16*w + (lane >> 2);
#pragma unroll
    for (int nt = 0; nt < 16; nt++){
        int c0 = 8*nt + 2*(lane & 3);
        __nv_bfloat162 h0 = __floats2bfloat162_rn(acc[nt][0], acc[nt][1]);
        __nv_bfloat162 h1 = __floats2bfloat162_rn(acc[nt][2], acc[nt][3]);
        *(uint32_t*)(Ob + (size_t)r0*UU + c0)       = *(uint32_t*)&h0;
        *(uint32_t*)(Ob + (size_t)(r0 + 8)*UU + c0) = *(uint32_t*)&h1;
    }
}

// ===========================================================================
// Output projection on mma.sync (occ 2)
// ===========================================================================
#define PROJ_SMEM 65536
__global__ void __launch_bounds__(256, 2)
proj_mma(const __nv_bfloat16* __restrict__ Ab, const __nv_bfloat16* __restrict__ Wob,
         float* __restrict__ C, const float* __restrict__ bias,
         const float* __restrict__ res)
{
    extern __shared__ __align__(128) char sm[];
    const uint32_t sb = smem_u32(sm);
    const int t = threadIdx.x, w = t >> 5, lane = t & 31, l7 = lane & 7;
    const int rowBase = blockIdx.y * 128, colBase = blockIdx.x * 128;

    const char* Ag = (const char*)(Ab + (size_t)rowBase * UU);
    const char* Wg = (const char*)Wob + (size_t)colBase * 2;
#pragma unroll
    for (int q = 0; q < 8; q++){
        int idx = t + q*256, row = idx >> 4, ch = idx & 15;
        uint32_t sw = (uint32_t)((ch ^ (row & 7)) << 4);
        CP16(sb + row*256 + sw,         Ag + (size_t)row*256 + ch*16);
        CP16(sb + 32768 + row*256 + sw, Wg + (size_t)row*512 + ch*16);
    }
    CP_COMMIT();
    CP_WAIT0();
    __syncthreads();

    float acc[16][4];
#pragma unroll
    for (int i = 0; i < 16; i++)
#pragma unroll
        for (int j = 0; j < 4; j++) acc[i][j] = 0.f;

#pragma unroll
    for (int t4 = 0; t4 < 8; t4++){
        uint32_t a[4];
        int arow = 16*w + (lane & 15);
        int ach  = 2*t4 + (lane >> 4);
        ldsm_x4(a, sb + arow*256 + (uint32_t)((ach ^ (arow & 7)) << 4));
        int krow = 16*t4 + l7 + ((lane >> 3) & 1)*8;
#pragma unroll
        for (int u2 = 0; u2 < 8; u2++){
            uint32_t bv[4];
            int ch = 2*u2 + (lane >> 4);
            ldsm_x4_t(bv, sb + 32768 + krow*256 + (uint32_t)((ch ^ l7) << 4));
            mma_bf16(acc[2*u2],     a, bv);
            mma_bf16(acc[2*u2 + 1], a, bv + 2);
        }
    }

    int r0 = rowBase + 16*w + (lane >> 2);
#pragma unroll
    for (int nt = 0; nt < 16; nt++){
        int c0 = colBase + 8*nt + 2*(lane & 3);
        float2 bi = *(const float2*)(bias + c0);
        float2 x0 = *(const float2*)(res + (size_t)r0*DD + c0);
        float2 x1 = *(const float2*)(res + (size_t)(r0 + 8)*DD + c0);
        *(float2*)(C + (size_t)r0*DD + c0) =
            make_float2(acc[nt][0] + bi.x + x0.x, acc[nt][1] + bi.y + x0.y);
        *(float2*)(C + (size_t)(r0 + 8)*DD + c0) =
            make_float2(acc[nt][2] + bi.x + x1.x, acc[nt][3] + bi.y + x1.y);
    }
}

// ===========================================================================
// Flash attention, m32 warp tile + key-split:
// 8 warps = 4 q-groups (32 rows) x 2 key-groups (32 keys per 64-key tile).
// Each B-fragment (ldmatrix 512B) feeds 4 MMAs -> smem-read cyc halved.
// End: key-group pair combines O partials + row sums through smem.
// ===========================================================================
#define ATT_OSTRIDE 136                      // float stride, bank-offset 8
#define ATT_SMEM (128*ATT_OSTRIDE*4 + 512)   // >= 64KB KV region too

__device__ __forceinline__ void load_kv(uint32_t dst, const char* Kg, const char* Vg,
                                        int tile, int t){
    const char* ks = Kg + (size_t)tile * 64 * 256;
    const char* vs = Vg + (size_t)tile * 64 * 256;
#pragma unroll
    for (int q = 0; q < 4; q++){
        int idx = t + q*256;
        int row = idx >> 4, ch = idx & 15;
        uint32_t d = dst + row*256 + (uint32_t)((ch ^ (row & 7)) << 4);
        CP16(d,         ks + (size_t)row*256 + ch*16);
        CP16(d + 16384, vs + (size_t)row*256 + ch*16);
    }
    CP_COMMIT();
}

__global__ void __launch_bounds__(256, 1)
attn_mma(const __nv_bfloat16* __restrict__ Q, const __nv_bfloat16* __restrict__ K,
         const __nv_bfloat16* __restrict__ V, __nv_bfloat16* __restrict__ O)
{
    extern __shared__ __align__(128) char sm[];
    const uint32_t sb = smem_u32(sm);
    const int t = threadIdx.x, w = t >> 5, lane = t & 31, l7 = lane & 7;
    const int qg = w & 3, kg = w >> 2;
    const int b = blockIdx.y, qb = blockIdx.x;

    // ---- stage Q (128x128 bf16, 32KB) then load A-fragments (regs) ----
    const char* Qg = (const char*)(Q + (size_t)(b*SS + qb*128)*UU);
#pragma unroll
    for (int q = 0; q < 8; q++){
        int idx = t + q*256;
        int row = idx >> 4, ch = idx & 15;
        CP16(sb + row*256 + (uint32_t)((ch ^ (row & 7)) << 4),
             Qg + (size_t)row*256 + ch*16);
    }
    CP_COMMIT();
    CP_WAIT0();
    __syncthreads();

    uint32_t qa[2][8][4];
#pragma unroll
    for (int rb = 0; rb < 2; rb++){
        int row = 32*qg + 16*rb + (lane & 15);
        int rx  = row & 7;
        int cb  = (lane >> 4) & 1;
#pragma unroll
        for (int kt = 0; kt < 8; kt++){
            int chunk = 2*kt + cb;
            ldsm_x4(qa[rb][kt], sb + row*256 + (uint32_t)((chunk ^ rx) << 4));
        }
    }
    __syncthreads();

    float oa[2][16][4];
#pragma unroll
    for (int rb = 0; rb < 2; rb++)
#pragma unroll
        for (int i = 0; i < 16; i++)
#pragma unroll
            for (int j = 0; j < 4; j++) oa[rb][i][j] = 0.f;
    float ls[2][2] = {{0.f,0.f},{0.f,0.f}};

    const char* Kg = (const char*)(K + (size_t)(b*SS)*UU);
    const char* Vg = (const char*)(V + (size_t)(b*SS)*UU);

    load_kv(sb,         Kg, Vg, 0, t);
    load_kv(sb + 32768, Kg, Vg, 1, t);

    const float C = 0.12751751699104088f;   // log2(e) / sqrt(128)

    for (int i = 0; i < 32; i++){
        if (i < 31) CP_WAIT1(); else CP_WAIT0();
        __syncthreads();
        const uint32_t kbuf = sb + (uint32_t)(i & 1)*32768;
        const uint32_t vbuf = kbuf + 16384;

#pragma unroll
        for (int tt2 = 0; tt2 < 2; tt2++){          // 16-key groups in my half
            const int kb = 32*kg + 16*tt2;
            float sa[2][2][4];
#pragma unroll
            for (int rb = 0; rb < 2; rb++)
#pragma unroll
                for (int jj = 0; jj < 2; jj++)
#pragma unroll
                    for (int j = 0; j < 4; j++) sa[rb][jj][j] = 0.f;
#pragma unroll
            for (int jj = 0; jj < 2; jj++){
                int row = kb + 8*jj + l7;
#pragma unroll
                for (int c = 0; c < 4; c++){
                    uint32_t bv[4];
                    int chunk = 4*c + (lane >> 3);
                    ldsm_x4(bv, kbuf + row*256 + (uint32_t)((chunk ^ l7) << 4));
                    mma_bf16(sa[0][jj], qa[0][2*c],   bv);
                    mma_bf16(sa[0][jj], qa[0][2*c+1], bv + 2);
                    mma_bf16(sa[1][jj], qa[1][2*c],   bv);
                    mma_bf16(sa[1][jj], qa[1][2*c+1], bv + 2);
                }
            }
            uint32_t pa[2][4];
#pragma unroll
            for (int rb = 0; rb < 2; rb++){
                float e00 = ex2f(sa[rb][0][0]*C), e01 = ex2f(sa[rb][0][1]*C);
                float e02 = ex2f(sa[rb][0][2]*C), e03 = ex2f(sa[rb][0][3]*C);
                float e10 = ex2f(sa[rb][1][0]*C), e11 = ex2f(sa[rb][1][1]*C);
                float e12 = ex2f(sa[rb][1][2]*C), e13 = ex2f(sa[rb][1][3]*C);
                ls[rb][0] += e00 + e01 + e10 + e11;
                ls[rb][1] += e02 + e03 + e12 + e13;
                __nv_bfloat162 h;
                h = __floats2bfloat162_rn(e00, e01); pa[rb][0] = *(uint32_t*)&h;
                h = __floats2bfloat162_rn(e02, e03); pa[rb][1] = *(uint32_t*)&h;
                h = __floats2bfloat162_rn(e10, e11); pa[rb][2] = *(uint32_t*)&h;
                h = __floats2bfloat162_rn(e12, e13); pa[rb][3] = *(uint32_t*)&h;
            }
            int vrow = kb + l7 + ((lane >> 3) & 1) * 8;
#pragma unroll
            for (int u2 = 0; u2 < 8; u2++){
                uint32_t bv[4];
                int chunk = 2*u2 + (lane >> 4);
                ldsm_x4_t(bv, vbuf + vrow*256 + (uint32_t)((chunk ^ l7) << 4));
                mma_bf16(oa[0][2*u2],     pa[0], bv);
                mma_bf16(oa[0][2*u2 + 1], pa[0], bv + 2);
                mma_bf16(oa[1][2*u2],     pa[1], bv);
                mma_bf16(oa[1][2*u2 + 1], pa[1], bv + 2);
            }
        }
        if (i < 30){
            __syncthreads();
            load_kv(sb + (uint32_t)(i & 1)*32768, Kg, Vg, i + 2, t);
        }
    }

    // ---- quad-reduce partial row sums ----
#pragma unroll
    for (int rb = 0; rb < 2; rb++)
#pragma unroll
        for (int j = 0; j < 2; j++){
            ls[rb][j] += __shfl_xor_sync(0xffffffffu, ls[rb][j], 1);
            ls[rb][j] += __shfl_xor_sync(0xffffffffu, ls[rb][j], 2);
        }

    // ---- combine key-group partials through smem (KV region is now free) ----
    float* smO = (float*)sm;
    float* smL = (float*)(sm + 128*ATT_OSTRIDE*4);
    __syncthreads();
    if (kg == 1){
#pragma unroll
        for (int rb = 0; rb < 2; rb++){
            int r0 = 32*qg + 16*rb + (lane >> 2);
            int c0 = 2*(lane & 3);
#pragma unroll
            for (int nt = 0; nt < 16; nt++){
                smO[r0*ATT_OSTRIDE + nt*8 + c0]           = oa[rb][nt][0];
                smO[r0*ATT_OSTRIDE + nt*8 + c0 + 1]       = oa[rb][nt][1];
                smO[(r0 + 8)*ATT_OSTRIDE + nt*8 + c0]     = oa[rb][nt][2];
                smO[(r0 + 8)*ATT_OSTRIDE + nt*8 + c0 + 1] = oa[rb][nt][3];
            }
            if ((lane & 3) == 0){
                smL[r0]     = ls[rb][0];
                smL[r0 + 8] = ls[rb][1];
            }
        }
    }
    __syncthreads();
    if (kg == 0){
#pragma unroll
        for (int rb = 0; rb < 2; rb++){
            int r0 = 32*qg + 16*rb + (lane >> 2);
            int c0 = 2*(lane & 3);
            float inv0 = 1.f / (ls[rb][0] + smL[r0]);
            float inv1 = 1.f / (ls[rb][1] + smL[r0 + 8]);
            __nv_bfloat16* Og = O + (size_t)(b*SS + qb*128 + r0)*UU + c0;
#pragma unroll
            for (int nt = 0; nt < 16; nt++){
                float o0 = (oa[rb][nt][0] + smO[r0*ATT_OSTRIDE + nt*8 + c0])           * inv0;
                float o1 = (oa[rb][nt][1] + smO[r0*ATT_OSTRIDE + nt*8 + c0 + 1])       * inv0;
                float o2 = (oa[rb][nt][2] + smO[(r0 + 8)*ATT_OSTRIDE + nt*8 + c0])     * inv1;
                float o3 = (oa[rb][nt][3] + smO[(r0 + 8)*ATT_OSTRIDE + nt*8 + c0 + 1]) * inv1;
                __nv_bfloat162 h0 = __floats2bfloat162_rn(o0, o1);
                __nv_bfloat162 h1 = __floats2bfloat162_rn(o2, o3);
                *(uint32_t*)(Og + nt*8)        = *(uint32_t*)&h0;
                *(uint32_t*)(Og + 8*UU + nt*8) = *(uint32_t*)&h1;
            }
        }
    }
}

// ===========================================================================
extern "C" void kernel_launch(void* const* d_in, const int* in_sizes, int n_in,
                              void* d_out, int out_size)
{
    const float* X   = (const float*)d_in[0];
    const float* W_q = (const float*)d_in[1];
    const float* W_k = (const float*)d_in[2];
    const float* W_v = (const float*)d_in[3];
    const float* W_o = (const float*)d_in[4];
    const float* b_o = (const float*)d_in[5];
    float* out = (float*)d_out;

    __nv_bfloat16 *xb, *qb, *kb, *vb, *ob, *wq, *wk, *wv, *wo;
    cudaGetSymbolAddress((void**)&xb, g_Xb);
    cudaGetSymbolAddress((void**)&qb, g_Qb);
    cudaGetSymbolAddress((void**)&kb, g_Kb);
    cudaGetSymbolAddress((void**)&vb, g_Vb);
    cudaGetSymbolAddress((void**)&ob, g_Ob);
    cudaGetSymbolAddress((void**)&wq, g_Wq);
    cudaGetSymbolAddress((void**)&wk, g_Wk);
    cudaGetSymbolAddress((void**)&wv, g_Wv);
    cudaGetSymbolAddress((void**)&wo, g_Wo);

    cudaFuncSetAttribute(qkv_mma,  cudaFuncAttributeMaxDynamicSharedMemorySize, QKV_SMEM);
    cudaFuncSetAttribute(attn_mma, cudaFuncAttributeMaxDynamicSharedMemorySize, ATT_SMEM);
    cudaFuncSetAttribute(proj_mma, cudaFuncAttributeMaxDynamicSharedMemorySize, PROJ_SMEM);

    conv_all<<<(NX4 + 4*NW4 + 255)/256, 256>>>(X, W_q, W_k, W_v, W_o,
                                               xb, wq, wk, wv, wo);
    qkv_mma<<<dim3(MM/128, 3), 256, QKV_SMEM>>>(xb, wq, wk, wv, qb, kb, vb);
    attn_mma<<<dim3(SS/128, BB), 256, ATT_SMEM>>>(qb, kb, vb, ob);
    proj_mma<<<dim3(DD/128, MM/128), 256, PROJ_SMEM>>>(ob, wo, out, b_o, X);
}

// round 8
// speedup vs baseline: 1.1832x; 1.0224x over previous
#include <cuda_runtime.h>
#include <cuda_bf16.h>
#include <cstdint>

#define BB 8
#define SS 2048
#define DD 256
#define UU 128
#define MM (BB*SS)

// ---------------- device scratch (bf16 staging) ----------------
__device__ __nv_bfloat16 g_Xb[MM*DD];
__device__ __nv_bfloat16 g_Qb[MM*UU];
__device__ __nv_bfloat16 g_Kb[MM*UU];
__device__ __nv_bfloat16 g_Vb[MM*UU];
__device__ __nv_bfloat16 g_Ob[MM*UU];
__device__ __nv_bfloat16 g_Wq[DD*UU], g_Wk[DD*UU], g_Wv[DD*UU];
__device__ __nv_bfloat16 g_Wo[UU*DD];

// ---------------- helpers ----------------
__device__ __forceinline__ uint32_t smem_u32(const void* p){
    uint32_t a;
    asm("{ .reg .u64 t; cvta.to.shared.u64 t, %1; cvt.u32.u64 %0, t; }":"=r"(a):"l"(p));
    return a;
}
__device__ __forceinline__ float ex2f(float x){
    float r; asm("ex2.approx.ftz.f32 %0, %1;":"=f"(r):"f"(x)); return r;
}
__device__ __forceinline__ void mma_bf16(float* c, const uint32_t* a, const uint32_t* b){
    asm volatile("mma.sync.aligned.m16n8k16.row.col.f32.bf16.bf16.f32 "
        "{%0,%1,%2,%3}, {%4,%5,%6,%7}, {%8,%9}, {%0,%1,%2,%3};"
        : "+f"(c[0]),"+f"(c[1]),"+f"(c[2]),"+f"(c[3])
        : "r"(a[0]),"r"(a[1]),"r"(a[2]),"r"(a[3]), "r"(b[0]),"r"(b[1]));
}
__device__ __forceinline__ void ldsm_x4(uint32_t* r, uint32_t addr){
    asm volatile("ldmatrix.sync.aligned.m8n8.x4.shared.b16 {%0,%1,%2,%3}, [%4];"
        : "=r"(r[0]),"=r"(r[1]),"=r"(r[2]),"=r"(r[3]) : "r"(addr));
}
__device__ __forceinline__ void ldsm_x4_t(uint32_t* r, uint32_t addr){
    asm volatile("ldmatrix.sync.aligned.m8n8.x4.trans.shared.b16 {%0,%1,%2,%3}, [%4];"
        : "=r"(r[0]),"=r"(r[1]),"=r"(r[2]),"=r"(r[3]) : "r"(addr));
}
#define CP16(dst, src) asm volatile("cp.async.cg.shared.global [%0], [%1], 16;" :: "r"(dst), "l"(src) : "memory")
#define CP_COMMIT()    asm volatile("cp.async.commit_group;" ::: "memory")
#define CP_WAIT0()     asm volatile("cp.async.wait_group 0;" ::: "memory")
#define CP_WAIT1()     asm volatile("cp.async.wait_group 1;" ::: "memory")

// ===========================================================================
// Fused fp32 -> bf16 convert (one launch)
// ===========================================================================
#define NX4 (MM*DD/4)
#define NW4 (DD*UU/4)
__global__ void conv_all(const float* __restrict__ X,
                         const float* __restrict__ Wq, const float* __restrict__ Wk,
                         const float* __restrict__ Wv, const float* __restrict__ Wo,
                         __nv_bfloat16* __restrict__ xb,
                         __nv_bfloat16* __restrict__ wq, __nv_bfloat16* __restrict__ wk,
                         __nv_bfloat16* __restrict__ wv, __nv_bfloat16* __restrict__ wo)
{
    int i = blockIdx.x * blockDim.x + threadIdx.x;
    const float* src; __nv_bfloat16* dst; int j;
    if (i < NX4)              { src = X;  dst = xb; j = i; }
    else if (i < NX4 + NW4)   { src = Wq; dst = wq; j = i - NX4; }
    else if (i < NX4 + 2*NW4) { src = Wk; dst = wk; j = i - NX4 - NW4; }
    else if (i < NX4 + 3*NW4) { src = Wv; dst = wv; j = i - NX4 - 2*NW4; }
    else if (i < NX4 + 4*NW4) { src = Wo; dst = wo; j = i - NX4 - 3*NW4; }
    else return;
    float4 v = ((const float4*)src)[j];
    __nv_bfloat162 a = __floats2bfloat162_rn(v.x, v.y);
    __nv_bfloat162 b = __floats2bfloat162_rn(v.z, v.w);
    uint2 o; o.x = *(uint32_t*)&a; o.y = *(uint32_t*)&b;
    ((uint2*)dst)[j] = o;
}

// ===========================================================================
// QKV projection: 64-row tiles, 8 warps = 4 row-groups x 2 col-groups, occ 3.
// smem: X 2x8KB + W 2x16KB = 48KB. K chunks of 64, double buffered.
// ===========================================================================
#define QKV_SMEM 49152
__global__ void __launch_bounds__(256, 3)
qkv_mma(const __nv_bfloat16* __restrict__ Xb,
        const __nv_bfloat16* __restrict__ Wqb, const __nv_bfloat16* __restrict__ Wkb,
        const __nv_bfloat16* __restrict__ Wvb,
        __nv_bfloat16* __restrict__ Qb, __nv_bfloat16* __restrict__ Kb,
        __nv_bfloat16* __restrict__ Vb)
{
    extern __shared__ __align__(128) char sm[];
    const uint32_t sb = smem_u32(sm);
    const int t = threadIdx.x, w = t >> 5, lane = t & 31, l7 = lane & 7;
    const int qg = w & 3, cg = w >> 2;
    const int z = blockIdx.y;
    const __nv_bfloat16* Wb = (z == 0) ? Wqb : (z == 1) ? Wkb : Wvb;
    __nv_bfloat16* Ob = (z == 0) ? Qb : (z == 1) ? Kb : Vb;
    const int rowBase = blockIdx.x * 64;
    const char* Xg = (const char*)(Xb + (size_t)rowBase * DD);
    const char* Wg = (const char*)Wb;

    auto load_chunk = [&](int kc, int buf){
        uint32_t xd = sb + (uint32_t)buf * 8192;            // X: 64 x 64 bf16, 128B rows
#pragma unroll
        for (int q = 0; q < 2; q++){
            int idx = t + q*256, row = idx >> 3, ch = idx & 7;
            CP16(xd + row*128 + (uint32_t)((ch ^ (row & 7)) << 4),
                 Xg + (size_t)row*512 + kc*128 + ch*16);
        }
        uint32_t wd = sb + 16384 + (uint32_t)buf * 16384;   // W: 64 x 128 bf16, 256B rows
#pragma unroll
        for (int q = 0; q < 4; q++){
            int idx = t + q*256, row = idx >> 4, ch = idx & 15;
            CP16(wd + row*256 + (uint32_t)((ch ^ (row & 7)) << 4),
                 Wg + (size_t)(kc*64 + row)*256 + ch*16);
        }
        CP_COMMIT();
    };

    float acc[8][4];
#pragma unroll
    for (int i = 0; i < 8; i++)
#pragma unroll
        for (int j = 0; j < 4; j++) acc[i][j] = 0.f;

    load_chunk(0, 0);
    load_chunk(1, 1);

    for (int kc = 0; kc < 4; kc++){
        if (kc < 3) CP_WAIT1(); else CP_WAIT0();
        __syncthreads();
        const uint32_t xb = sb + (uint32_t)(kc & 1)*8192;
        const uint32_t wb = sb + 16384 + (uint32_t)(kc & 1)*16384;
#pragma unroll
        for (int t4 = 0; t4 < 4; t4++){
            uint32_t a[4];
            int arow = 16*qg + (lane & 15);
            int ach  = 2*t4 + (lane >> 4);
            ldsm_x4(a, xb + arow*128 + (uint32_t)((ach ^ (arow & 7)) << 4));
            int krow = 16*t4 + l7 + ((lane >> 3) & 1)*8;
#pragma unroll
            for (int u2 = 0; u2 < 4; u2++){
                uint32_t bv[4];
                int ch = 2*(4*cg + u2) + (lane >> 4);
                ldsm_x4_t(bv, wb + krow*256 + (uint32_t)((ch ^ l7) << 4));
                mma_bf16(acc[2*u2],     a, bv);
                mma_bf16(acc[2*u2 + 1], a, bv + 2);
            }
        }
        if (kc < 2){ __syncthreads(); load_chunk(kc + 2, kc & 1); }
    }

    int r0 = rowBase + 16*qg + (lane >> 2);
#pragma unroll
    for (int nt = 0; nt < 8; nt++){
        int c0 = 64*cg + 8*nt + 2*(lane & 3);
        __nv_bfloat162 h0 = __floats2bfloat162_rn(acc[nt][0], acc[nt][1]);
        __nv_bfloat162 h1 = __floats2bfloat162_rn(acc[nt][2], acc[nt][3]);
        *(uint32_t*)(Ob + (size_t)r0*UU + c0)       = *(uint32_t*)&h0;
        *(uint32_t*)(Ob + (size_t)(r0 + 8)*UU + c0) = *(uint32_t*)&h1;
    }
}

// ===========================================================================
// Output projection: 64x128 tiles, 8 warps = 4 row-groups x 2 col-groups, occ 3.
// smem: A 16KB + W 32KB = 48KB. K=128 single load.
// ===========================================================================
#define PROJ_SMEM 49152
__global__ void __launch_bounds__(256, 3)
proj_mma(const __nv_bfloat16* __restrict__ Ab, const __nv_bfloat16* __restrict__ Wob,
         float* __restrict__ C, const float* __restrict__ bias,
         const float* __restrict__ res)
{
    extern __shared__ __align__(128) char sm[];
    const uint32_t sb = smem_u32(sm);
    const int t = threadIdx.x, w = t >> 5, lane = t & 31, l7 = lane & 7;
    const int qg = w & 3, cg = w >> 2;
    const int rowBase = blockIdx.y * 64, colBase = blockIdx.x * 128;

    const char* Ag = (const char*)(Ab + (size_t)rowBase * UU);
    const char* Wg = (const char*)Wob + (size_t)colBase * 2;
    // A: 64 x 128 bf16 (256B rows) @ sb
#pragma unroll
    for (int q = 0; q < 4; q++){
        int idx = t + q*256, row = idx >> 4, ch = idx & 15;
        CP16(sb + row*256 + (uint32_t)((ch ^ (row & 7)) << 4),
             Ag + (size_t)row*256 + ch*16);
    }
    // W: 128 x 128 bf16 (256B rows) @ sb + 16384
#pragma unroll
    for (int q = 0; q < 8; q++){
        int idx = t + q*256, row = idx >> 4, ch = idx & 15;
        CP16(sb + 16384 + row*256 + (uint32_t)((ch ^ (row & 7)) << 4),
             Wg + (size_t)row*512 + ch*16);
    }
    CP_COMMIT();
    CP_WAIT0();
    __syncthreads();

    float acc[8][4];
#pragma unroll
    for (int i = 0; i < 8; i++)
#pragma unroll
        for (int j = 0; j < 4; j++) acc[i][j] = 0.f;

#pragma unroll
    for (int t4 = 0; t4 < 8; t4++){
        uint32_t a[4];
        int arow = 16*qg + (lane & 15);
        int ach  = 2*t4 + (lane >> 4);
        ldsm_x4(a, sb + arow*256 + (uint32_t)((ach ^ (arow & 7)) << 4));
        int krow = 16*t4 + l7 + ((lane >> 3) & 1)*8;
#pragma unroll
        for (int u2 = 0; u2 < 4; u2++){
            uint32_t bv[4];
            int ch = 2*(4*cg + u2) + (lane >> 4);
            ldsm_x4_t(bv, sb + 16384 + krow*256 + (uint32_t)((ch ^ l7) << 4));
            mma_bf16(acc[2*u2],     a, bv);
            mma_bf16(acc[2*u2 + 1], a, bv + 2);
        }
    }

    int r0 = rowBase + 16*qg + (lane >> 2);
#pragma unroll
    for (int nt = 0; nt < 8; nt++){
        int c0 = colBase + 64*cg + 8*nt + 2*(lane & 3);
        float2 bi = *(const float2*)(bias + c0);
        float2 x0 = *(const float2*)(res + (size_t)r0*DD + c0);
        float2 x1 = *(const float2*)(res + (size_t)(r0 + 8)*DD + c0);
        *(float2*)(C + (size_t)r0*DD + c0) =
            make_float2(acc[nt][0] + bi.x + x0.x, acc[nt][1] + bi.y + x0.y);
        *(float2*)(C + (size_t)(r0 + 8)*DD + c0) =
            make_float2(acc[nt][2] + bi.x + x1.x, acc[nt][3] + bi.y + x1.y);
    }
}

// ===========================================================================
// Flash attention, m32 warp tile + key-split, 128-key tiles (16 iterations).
// 8 warps = 4 q-groups (32 rows) x 2 key-groups (64 keys per 128-key tile).
// smem: 2 stages x (K 32KB + V 32KB) = 128KB; Q staged in stage-0 region first.
// ===========================================================================
#define ATT_OSTRIDE 136
#define ATT_SMEM 131072

__device__ __forceinline__ void load_kv(uint32_t dst, const char* Kg, const char* Vg,
                                        int tile, int t){
    const char* ks = Kg + (size_t)tile * 128 * 256;
    const char* vs = Vg + (size_t)tile * 128 * 256;
#pragma unroll
    for (int q = 0; q < 8; q++){
        int idx = t + q*256;            // 0..2047
        int row = idx >> 4, ch = idx & 15;
        uint32_t d = dst + row*256 + (uint32_t)((ch ^ (row & 7)) << 4);
        CP16(d,         ks + (size_t)row*256 + ch*16);
        CP16(d + 32768, vs + (size_t)row*256 + ch*16);
    }
    CP_COMMIT();
}

__global__ void __launch_bounds__(256, 1)
attn_mma(const __nv_bfloat16* __restrict__ Q, const __nv_bfloat16* __restrict__ K,
         const __nv_bfloat16* __restrict__ V, __nv_bfloat16* __restrict__ O)
{
    extern __shared__ __align__(128) char sm[];
    const uint32_t sb = smem_u32(sm);
    const int t = threadIdx.x, w = t >> 5, lane = t & 31, l7 = lane & 7;
    const int qg = w & 3, kg = w >> 2;
    const int b = blockIdx.y, qb = blockIdx.x;

    // ---- stage Q (128x128 bf16, 32KB) then load A-fragments ----
    const char* Qg = (const char*)(Q + (size_t)(b*SS + qb*128)*UU);
#pragma unroll
    for (int q = 0; q < 8; q++){
        int idx = t + q*256;
        int row = idx >> 4, ch = idx & 15;
        CP16(sb + row*256 + (uint32_t)((ch ^ (row & 7)) << 4),
             Qg + (size_t)row*256 + ch*16);
    }
    CP_COMMIT();
    CP_WAIT0();
    __syncthreads();

    uint32_t qa[2][8][4];
#pragma unroll
    for (int rb = 0; rb < 2; rb++){
        int row = 32*qg + 16*rb + (lane & 15);
        int rx  = row & 7;
        int cb  = (lane >> 4) & 1;
#pragma unroll
        for (int kt = 0; kt < 8; kt++){
            int chunk = 2*kt + cb;
            ldsm_x4(qa[rb][kt], sb + row*256 + (uint32_t)((chunk ^ rx) << 4));
        }
    }
    __syncthreads();

    float oa[2][16][4];
#pragma unroll
    for (int rb = 0; rb < 2; rb++)
#pragma unroll
        for (int i = 0; i < 16; i++)
#pragma unroll
            for (int j = 0; j < 4; j++) oa[rb][i][j] = 0.f;
    float ls[2][2] = {{0.f,0.f},{0.f,0.f}};

    const char* Kg = (const char*)(K + (size_t)(b*SS)*UU);
    const char* Vg = (const char*)(V + (size_t)(b*SS)*UU);

    load_kv(sb,         Kg, Vg, 0, t);
    load_kv(sb + 65536, Kg, Vg, 1, t);

    const float C = 0.12751751699104088f;   // log2(e) / sqrt(128)

    for (int i = 0; i < 16; i++){
        if (i < 15) CP_WAIT1(); else CP_WAIT0();
        __syncthreads();
        const uint32_t kbuf = sb + (uint32_t)(i & 1)*65536;
        const uint32_t vbuf = kbuf + 32768;

#pragma unroll
        for (int tt2 = 0; tt2 < 4; tt2++){          // 16-key groups in my 64-key half
            const int kb = 64*kg + 16*tt2;
            float sa[2][2][4];
#pragma unroll
            for (int rb = 0; rb < 2; rb++)
#pragma unroll
                for (int jj = 0; jj < 2; jj++)
#pragma unroll
                    for (int j = 0; j < 4; j++) sa[rb][jj][j] = 0.f;
#pragma unroll
            for (int jj = 0; jj < 2; jj++){
                int row = kb + 8*jj + l7;
#pragma unroll
                for (int c = 0; c < 4; c++){
                    uint32_t bv[4];
                    int chunk = 4*c + (lane >> 3);
                    ldsm_x4(bv, kbuf + row*256 + (uint32_t)((chunk ^ l7) << 4));
                    mma_bf16(sa[0][jj], qa[0][2*c],   bv);
                    mma_bf16(sa[0][jj], qa[0][2*c+1], bv + 2);
                    mma_bf16(sa[1][jj], qa[1][2*c],   bv);
                    mma_bf16(sa[1][jj], qa[1][2*c+1], bv + 2);
                }
            }
            uint32_t pa[2][4];
#pragma unroll
            for (int rb = 0; rb < 2; rb++){
                float e00 = ex2f(sa[rb][0][0]*C), e01 = ex2f(sa[rb][0][1]*C);
                float e02 = ex2f(sa[rb][0][2]*C), e03 = ex2f(sa[rb][0][3]*C);
                float e10 = ex2f(sa[rb][1][0]*C), e11 = ex2f(sa[rb][1][1]*C);
                float e12 = ex2f(sa[rb][1][2]*C), e13 = ex2f(sa[rb][1][3]*C);
                ls[rb][0] += e00 + e01 + e10 + e11;
                ls[rb][1] += e02 + e03 + e12 + e13;
                __nv_bfloat162 h;
                h = __floats2bfloat162_rn(e00, e01); pa[rb][0] = *(uint32_t*)&h;
                h = __floats2bfloat162_rn(e02, e03); pa[rb][1] = *(uint32_t*)&h;
                h = __floats2bfloat162_rn(e10, e11); pa[rb][2] = *(uint32_t*)&h;
                h = __floats2bfloat162_rn(e12, e13); pa[rb][3] = *(uint32_t*)&h;
            }
            int vrow = kb + l7 + ((lane >> 3) & 1) * 8;
#pragma unroll
            for (int u2 = 0; u2 < 8; u2++){
                uint32_t bv[4];
                int chunk = 2*u2 + (lane >> 4);
                ldsm_x4_t(bv, vbuf + vrow*256 + (uint32_t)((chunk ^ l7) << 4));
                mma_bf16(oa[0][2*u2],     pa[0], bv);
                mma_bf16(oa[0][2*u2 + 1], pa[0], bv + 2);
                mma_bf16(oa[1][2*u2],     pa[1], bv);
                mma_bf16(oa[1][2*u2 + 1], pa[1], bv + 2);
            }
        }
        if (i < 14){
            __syncthreads();
            load_kv(sb + (uint32_t)(i & 1)*65536, Kg, Vg, i + 2, t);
        }
    }

    // ---- quad-reduce partial row sums ----
#pragma unroll
    for (int rb = 0; rb < 2; rb++)
#pragma unroll
        for (int j = 0; j < 2; j++){
            ls[rb][j] += __shfl_xor_sync(0xffffffffu, ls[rb][j], 1);
            ls[rb][j] += __shfl_xor_sync(0xffffffffu, ls[rb][j], 2);
        }

    // ---- combine key-group partials through smem ----
    float* smO = (float*)sm;
    float* smL = (float*)(sm + 128*ATT_OSTRIDE*4);
    __syncthreads();
    if (kg == 1){
#pragma unroll
        for (int rb = 0; rb < 2; rb++){
            int r0 = 32*qg + 16*rb + (lane >> 2);
            int c0 = 2*(lane & 3);
#pragma unroll
            for (int nt = 0; nt < 16; nt++){
                smO[r0*ATT_OSTRIDE + nt*8 + c0]           = oa[rb][nt][0];
                smO[r0*ATT_OSTRIDE + nt*8 + c0 + 1]       = oa[rb][nt][1];
                smO[(r0 + 8)*ATT_OSTRIDE + nt*8 + c0]     = oa[rb][nt][2];
                smO[(r0 + 8)*ATT_OSTRIDE + nt*8 + c0 + 1] = oa[rb][nt][3];
            }
            if ((lane & 3) == 0){
                smL[r0]     = ls[rb][0];
                smL[r0 + 8] = ls[rb][1];
            }
        }
    }
    __syncthreads();
    if (kg == 0){
#pragma unroll
        for (int rb = 0; rb < 2; rb++){
            int r0 = 32*qg + 16*rb + (lane >> 2);
            int c0 = 2*(lane & 3);
            float inv0 = 1.f / (ls[rb][0] + smL[r0]);
            float inv1 = 1.f / (ls[rb][1] + smL[r0 + 8]);
            __nv_bfloat16* Og = O + (size_t)(b*SS + qb*128 + r0)*UU + c0;
#pragma unroll
            for (int nt = 0; nt < 16; nt++){
                float o0 = (oa[rb][nt][0] + smO[r0*ATT_OSTRIDE + nt*8 + c0])           * inv0;
                float o1 = (oa[rb][nt][1] + smO[r0*ATT_OSTRIDE + nt*8 + c0 + 1])       * inv0;
                float o2 = (oa[rb][nt][2] + smO[(r0 + 8)*ATT_OSTRIDE + nt*8 + c0])     * inv1;
                float o3 = (oa[rb][nt][3] + smO[(r0 + 8)*ATT_OSTRIDE + nt*8 + c0 + 1]) * inv1;
                __nv_bfloat162 h0 = __floats2bfloat162_rn(o0, o1);
                __nv_bfloat162 h1 = __floats2bfloat162_rn(o2, o3);
                *(uint32_t*)(Og + nt*8)        = *(uint32_t*)&h0;
                *(uint32_t*)(Og + 8*UU + nt*8) = *(uint32_t*)&h1;
            }
        }
    }
}

// ===========================================================================
extern "C" void kernel_launch(void* const* d_in, const int* in_sizes, int n_in,
                              void* d_out, int out_size)
{
    const float* X   = (const float*)d_in[0];
    const float* W_q = (const float*)d_in[1];
    const float* W_k = (const float*)d_in[2];
    const float* W_v = (const float*)d_in[3];
    const float* W_o = (const float*)d_in[4];
    const float* b_o = (const float*)d_in[5];
    float* out = (float*)d_out;

    __nv_bfloat16 *xb, *qb, *kb, *vb, *ob, *wq, *wk, *wv, *wo;
    cudaGetSymbolAddress((void**)&xb, g_Xb);
    cudaGetSymbolAddress((void**)&qb, g_Qb);
    cudaGetSymbolAddress((void**)&kb, g_Kb);
    cudaGetSymbolAddress((void**)&vb, g_Vb);
    cudaGetSymbolAddress((void**)&ob, g_Ob);
    cudaGetSymbolAddress((void**)&wq, g_Wq);
    cudaGetSymbolAddress((void**)&wk, g_Wk);
    cudaGetSymbolAddress((void**)&wv, g_Wv);
    cudaGetSymbolAddress((void**)&wo, g_Wo);

    cudaFuncSetAttribute(qkv_mma,  cudaFuncAttributeMaxDynamicSharedMemorySize, QKV_SMEM);
    cudaFuncSetAttribute(attn_mma, cudaFuncAttributeMaxDynamicSharedMemorySize, ATT_SMEM);
    cudaFuncSetAttribute(proj_mma, cudaFuncAttributeMaxDynamicSharedMemorySize, PROJ_SMEM);

    conv_all<<<(NX4 + 4*NW4 + 255)/256, 256>>>(X, W_q, W_k, W_v, W_o,
                                               xb, wq, wk, wv, wo);
    qkv_mma<<<dim3(MM/64, 3), 256, QKV_SMEM>>>(xb, wq, wk, wv, qb, kb, vb);
    attn_mma<<<dim3(SS/128, BB), 256, ATT_SMEM>>>(qb, kb, vb, ob);
    proj_mma<<<dim3(DD/128, MM/64), 256, PROJ_SMEM>>>(ob, wo, out, b_o, X);
}

// round 9
// speedup vs baseline: 1.2182x; 1.0296x over previous
#include <cuda_runtime.h>
#include <cuda_bf16.h>
#include <cstdint>

#define BB 8
#define SS 2048
#define DD 256
#define UU 128
#define MM (BB*SS)

// ---------------- device scratch (bf16 staging) ----------------
__device__ __nv_bfloat16 g_Xb[MM*DD];
__device__ __nv_bfloat16 g_Qb[MM*UU];
__device__ __nv_bfloat16 g_Kb[MM*UU];
__device__ __nv_bfloat16 g_Vb[MM*UU];
__device__ __nv_bfloat16 g_Ob[MM*UU];
__device__ __nv_bfloat16 g_Wq[DD*UU], g_Wk[DD*UU], g_Wv[DD*UU];
__device__ __nv_bfloat16 g_Wo[UU*DD];

// ---------------- helpers ----------------
__device__ __forceinline__ uint32_t smem_u32(const void* p){
    uint32_t a;
    asm("{ .reg .u64 t; cvta.to.shared.u64 t, %1; cvt.u32.u64 %0, t; }":"=r"(a):"l"(p));
    return a;
}
__device__ __forceinline__ float ex2f(float x){
    float r; asm("ex2.approx.ftz.f32 %0, %1;":"=f"(r):"f"(x)); return r;
}
__device__ __forceinline__ void mma_bf16(float* c, const uint32_t* a, const uint32_t* b){
    asm volatile("mma.sync.aligned.m16n8k16.row.col.f32.bf16.bf16.f32 "
        "{%0,%1,%2,%3}, {%4,%5,%6,%7}, {%8,%9}, {%0,%1,%2,%3};"
        : "+f"(c[0]),"+f"(c[1]),"+f"(c[2]),"+f"(c[3])
        : "r"(a[0]),"r"(a[1]),"r"(a[2]),"r"(a[3]), "r"(b[0]),"r"(b[1]));
}
__device__ __forceinline__ void ldsm_x4(uint32_t* r, uint32_t addr){
    asm volatile("ldmatrix.sync.aligned.m8n8.x4.shared.b16 {%0,%1,%2,%3}, [%4];"
        : "=r"(r[0]),"=r"(r[1]),"=r"(r[2]),"=r"(r[3]) : "r"(addr));
}
__device__ __forceinline__ void ldsm_x4_t(uint32_t* r, uint32_t addr){
    asm volatile("ldmatrix.sync.aligned.m8n8.x4.trans.shared.b16 {%0,%1,%2,%3}, [%4];"
        : "=r"(r[0]),"=r"(r[1]),"=r"(r[2]),"=r"(r[3]) : "r"(addr));
}
#define CP16(dst, src) asm volatile("cp.async.cg.shared.global [%0], [%1], 16;" :: "r"(dst), "l"(src) : "memory")
#define CP_COMMIT()    asm volatile("cp.async.commit_group;" ::: "memory")
#define CP_WAIT0()     asm volatile("cp.async.wait_group 0;" ::: "memory")
#define CP_WAIT1()     asm volatile("cp.async.wait_group 1;" ::: "memory")

// ===========================================================================
// Fused fp32 -> bf16 convert (one launch)
// ===========================================================================
#define NX4 (MM*DD/4)
#define NW4 (DD*UU/4)
__global__ void conv_all(const float* __restrict__ X,
                         const float* __restrict__ Wq, const float* __restrict__ Wk,
                         const float* __restrict__ Wv, const float* __restrict__ Wo,
                         __nv_bfloat16* __restrict__ xb,
                         __nv_bfloat16* __restrict__ wq, __nv_bfloat16* __restrict__ wk,
                         __nv_bfloat16* __restrict__ wv, __nv_bfloat16* __restrict__ wo)
{
    int i = blockIdx.x * blockDim.x + threadIdx.x;
    const float* src; __nv_bfloat16* dst; int j;
    if (i < NX4)              { src = X;  dst = xb; j = i; }
    else if (i < NX4 + NW4)   { src = Wq; dst = wq; j = i - NX4; }
    else if (i < NX4 + 2*NW4) { src = Wk; dst = wk; j = i - NX4 - NW4; }
    else if (i < NX4 + 3*NW4) { src = Wv; dst = wv; j = i - NX4 - 2*NW4; }
    else if (i < NX4 + 4*NW4) { src = Wo; dst = wo; j = i - NX4 - 3*NW4; }
    else return;
    float4 v = ((const float4*)src)[j];
    __nv_bfloat162 a = __floats2bfloat162_rn(v.x, v.y);
    __nv_bfloat162 b = __floats2bfloat162_rn(v.z, v.w);
    uint2 o; o.x = *(uint32_t*)&a; o.y = *(uint32_t*)&b;
    ((uint2*)dst)[j] = o;
}

// ===========================================================================
// QKV projection: 64-row tiles, occ 3, smem-staged coalesced epilogue.
// ===========================================================================
#define QKV_SMEM 49152
__global__ void __launch_bounds__(256, 3)
qkv_mma(const __nv_bfloat16* __restrict__ Xb,
        const __nv_bfloat16* __restrict__ Wqb, const __nv_bfloat16* __restrict__ Wkb,
        const __nv_bfloat16* __restrict__ Wvb,
        __nv_bfloat16* __restrict__ Qb, __nv_bfloat16* __restrict__ Kb,
        __nv_bfloat16* __restrict__ Vb)
{
    extern __shared__ __align__(128) char sm[];
    const uint32_t sb = smem_u32(sm);
    const int t = threadIdx.x, w = t >> 5, lane = t & 31, l7 = lane & 7;
    const int qg = w & 3, cg = w >> 2;
    const int z = blockIdx.y;
    const __nv_bfloat16* Wb = (z == 0) ? Wqb : (z == 1) ? Wkb : Wvb;
    __nv_bfloat16* Ob = (z == 0) ? Qb : (z == 1) ? Kb : Vb;
    const int rowBase = blockIdx.x * 64;
    const char* Xg = (const char*)(Xb + (size_t)rowBase * DD);
    const char* Wg = (const char*)Wb;

    auto load_chunk = [&](int kc, int buf){
        uint32_t xd = sb + (uint32_t)buf * 8192;            // X: 64 x 64 bf16
#pragma unroll
        for (int q = 0; q < 2; q++){
            int idx = t + q*256, row = idx >> 3, ch = idx & 7;
            CP16(xd + row*128 + (uint32_t)((ch ^ (row & 7)) << 4),
                 Xg + (size_t)row*512 + kc*128 + ch*16);
        }
        uint32_t wd = sb + 16384 + (uint32_t)buf * 16384;   // W: 64 x 128 bf16
#pragma unroll
        for (int q = 0; q < 4; q++){
            int idx = t + q*256, row = idx >> 4, ch = idx & 15;
            CP16(wd + row*256 + (uint32_t)((ch ^ (row & 7)) << 4),
                 Wg + (size_t)(kc*64 + row)*256 + ch*16);
        }
        CP_COMMIT();
    };

    float acc[8][4];
#pragma unroll
    for (int i = 0; i < 8; i++)
#pragma unroll
        for (int j = 0; j < 4; j++) acc[i][j] = 0.f;

    load_chunk(0, 0);
    load_chunk(1, 1);

    for (int kc = 0; kc < 4; kc++){
        if (kc < 3) CP_WAIT1(); else CP_WAIT0();
        __syncthreads();
        const uint32_t xb = sb + (uint32_t)(kc & 1)*8192;
        const uint32_t wb = sb + 16384 + (uint32_t)(kc & 1)*16384;
#pragma unroll
        for (int t4 = 0; t4 < 4; t4++){
            uint32_t a[4];
            int arow = 16*qg + (lane & 15);
            int ach  = 2*t4 + (lane >> 4);
            ldsm_x4(a, xb + arow*128 + (uint32_t)((ach ^ (arow & 7)) << 4));
            int krow = 16*t4 + l7 + ((lane >> 3) & 1)*8;
#pragma unroll
            for (int u2 = 0; u2 < 4; u2++){
                uint32_t bv[4];
                int ch = 2*(4*cg + u2) + (lane >> 4);
                ldsm_x4_t(bv, wb + krow*256 + (uint32_t)((ch ^ l7) << 4));
                mma_bf16(acc[2*u2],     a, bv);
                mma_bf16(acc[2*u2 + 1], a, bv + 2);
            }
        }
        if (kc < 2){ __syncthreads(); load_chunk(kc + 2, kc & 1); }
    }

    // ---- staged coalesced epilogue: [64][68] u32 (bf16x2), stride pad ----
    __syncthreads();
    uint32_t* st = (uint32_t*)sm;
    {
        int r = 16*qg + (lane >> 2);
        int c2base = 32*cg + (lane & 3);
#pragma unroll
        for (int nt = 0; nt < 8; nt++){
            __nv_bfloat162 h0 = __floats2bfloat162_rn(acc[nt][0], acc[nt][1]);
            __nv_bfloat162 h1 = __floats2bfloat162_rn(acc[nt][2], acc[nt][3]);
            st[r*68 + c2base + 4*nt]       = *(uint32_t*)&h0;
            st[(r + 8)*68 + c2base + 4*nt] = *(uint32_t*)&h1;
        }
    }
    __syncthreads();
#pragma unroll
    for (int p = 0; p < 4; p++){
        int row = (t >> 4) + p*16;
        int u4  = t & 15;
        uint4 v = *(uint4*)(st + row*68 + u4*4);
        *(uint4*)(Ob + (size_t)(rowBase + row)*UU + u4*8) = v;
    }
}

// ===========================================================================
// Output projection: 64x128 tiles, occ 3, smem-staged coalesced epilogue.
// ===========================================================================
#define PROJ_SMEM 49152
__global__ void __launch_bounds__(256, 3)
proj_mma(const __nv_bfloat16* __restrict__ Ab, const __nv_bfloat16* __restrict__ Wob,
         float* __restrict__ C, const float* __restrict__ bias,
         const float* __restrict__ res)
{
    extern __shared__ __align__(128) char sm[];
    const uint32_t sb = smem_u32(sm);
    const int t = threadIdx.x, w = t >> 5, lane = t & 31, l7 = lane & 7;
    const int qg = w & 3, cg = w >> 2;
    const int rowBase = blockIdx.y * 64, colBase = blockIdx.x * 128;

    const char* Ag = (const char*)(Ab + (size_t)rowBase * UU);
    const char* Wg = (const char*)Wob + (size_t)colBase * 2;
#pragma unroll
    for (int q = 0; q < 4; q++){
        int idx = t + q*256, row = idx >> 4, ch = idx & 15;
        CP16(sb + row*256 + (uint32_t)((ch ^ (row & 7)) << 4),
             Ag + (size_t)row*256 + ch*16);
    }
#pragma unroll
    for (int q = 0; q < 8; q++){
        int idx = t + q*256, row = idx >> 4, ch = idx & 15;
        CP16(sb + 16384 + row*256 + (uint32_t)((ch ^ (row & 7)) << 4),
             Wg + (size_t)row*512 + ch*16);
    }
    CP_COMMIT();
    CP_WAIT0();
    __syncthreads();

    float acc[8][4];
#pragma unroll
    for (int i = 0; i < 8; i++)
#pragma unroll
        for (int j = 0; j < 4; j++) acc[i][j] = 0.f;

#pragma unroll
    for (int t4 = 0; t4 < 8; t4++){
        uint32_t a[4];
        int arow = 16*qg + (lane & 15);
        int ach  = 2*t4 + (lane >> 4);
        ldsm_x4(a, sb + arow*256 + (uint32_t)((ach ^ (arow & 7)) << 4));
        int krow = 16*t4 + l7 + ((lane >> 3) & 1)*8;
#pragma unroll
        for (int u2 = 0; u2 < 4; u2++){
            uint32_t bv[4];
            int ch = 2*(4*cg + u2) + (lane >> 4);
            ldsm_x4_t(bv, sb + 16384 + krow*256 + (uint32_t)((ch ^ l7) << 4));
            mma_bf16(acc[2*u2],     a, bv);
            mma_bf16(acc[2*u2 + 1], a, bv + 2);
        }
    }

    // ---- staged coalesced epilogue: [64][132] fp32 ----
    __syncthreads();
    float* st = (float*)sm;
    {
        int r = 16*qg + (lane >> 2);
        int cb = 64*cg + 2*(lane & 3);
#pragma unroll
        for (int nt = 0; nt < 8; nt++){
            int c = cb + 8*nt;
            st[r*132 + c]           = acc[nt][0];
            st[r*132 + c + 1]       = acc[nt][1];
            st[(r + 8)*132 + c]     = acc[nt][2];
            st[(r + 8)*132 + c + 1] = acc[nt][3];
        }
    }
    __syncthreads();
#pragma unroll
    for (int p = 0; p < 8; p++){
        int row = (t >> 5) + p*8;
        int c4  = t & 31;
        float4 v  = *(float4*)(st + row*132 + c4*4);
        float4 bi = *(const float4*)(bias + colBase + c4*4);
        float4 rs = *(const float4*)(res + (size_t)(rowBase + row)*DD + colBase + c4*4);
        v.x += bi.x + rs.x; v.y += bi.y + rs.y;
        v.z += bi.z + rs.z; v.w += bi.w + rs.w;
        *(float4*)(C + (size_t)(rowBase + row)*DD + colBase + c4*4) = v;
    }
}

// ===========================================================================
// Flash attention, m32 warp tile + key-split, 128-key tiles, staged O output.
// ===========================================================================
#define ATT_OSTRIDE 136
#define ATT_STAGE   73728          // byte offset of output stage region
#define ATT_SMEM   131072

__device__ __forceinline__ void load_kv(uint32_t dst, const char* Kg, const char* Vg,
                                        int tile, int t){
    const char* ks = Kg + (size_t)tile * 128 * 256;
    const char* vs = Vg + (size_t)tile * 128 * 256;
#pragma unroll
    for (int q = 0; q < 8; q++){
        int idx = t + q*256;
        int row = idx >> 4, ch = idx & 15;
        uint32_t d = dst + row*256 + (uint32_t)((ch ^ (row & 7)) << 4);
        CP16(d,         ks + (size_t)row*256 + ch*16);
        CP16(d + 32768, vs + (size_t)row*256 + ch*16);
    }
    CP_COMMIT();
}

__global__ void __launch_bounds__(256, 1)
attn_mma(const __nv_bfloat16* __restrict__ Q, const __nv_bfloat16* __restrict__ K,
         const __nv_bfloat16* __restrict__ V, __nv_bfloat16* __restrict__ O)
{
    extern __shared__ __align__(128) char sm[];
    const uint32_t sb = smem_u32(sm);
    const int t = threadIdx.x, w = t >> 5, lane = t & 31, l7 = lane & 7;
    const int qg = w & 3, kg = w >> 2;
    const int b = blockIdx.y, qb = blockIdx.x;

    const char* Qg = (const char*)(Q + (size_t)(b*SS + qb*128)*UU);
#pragma unroll
    for (int q = 0; q < 8; q++){
        int idx = t + q*256;
        int row = idx >> 4, ch = idx & 15;
        CP16(sb + row*256 + (uint32_t)((ch ^ (row & 7)) << 4),
             Qg + (size_t)row*256 + ch*16);
    }
    CP_COMMIT();
    CP_WAIT0();
    __syncthreads();

    uint32_t qa[2][8][4];
#pragma unroll
    for (int rb = 0; rb < 2; rb++){
        int row = 32*qg + 16*rb + (lane & 15);
        int rx  = row & 7;
        int cb  = (lane >> 4) & 1;
#pragma unroll
        for (int kt = 0; kt < 8; kt++){
            int chunk = 2*kt + cb;
            ldsm_x4(qa[rb][kt], sb + row*256 + (uint32_t)((chunk ^ rx) << 4));
        }
    }
    __syncthreads();

    float oa[2][16][4];
#pragma unroll
    for (int rb = 0; rb < 2; rb++)
#pragma unroll
        for (int i = 0; i < 16; i++)
#pragma unroll
            for (int j = 0; j < 4; j++) oa[rb][i][j] = 0.f;
    float ls[2][2] = {{0.f,0.f},{0.f,0.f}};

    const char* Kg = (const char*)(K + (size_t)(b*SS)*UU);
    const char* Vg = (const char*)(V + (size_t)(b*SS)*UU);

    load_kv(sb,         Kg, Vg, 0, t);
    load_kv(sb + 65536, Kg, Vg, 1, t);

    const float C = 0.12751751699104088f;   // log2(e) / sqrt(128)

    for (int i = 0; i < 16; i++){
        if (i < 15) CP_WAIT1(); else CP_WAIT0();
        __syncthreads();
        const uint32_t kbuf = sb + (uint32_t)(i & 1)*65536;
        const uint32_t vbuf = kbuf + 32768;

#pragma unroll
        for (int tt2 = 0; tt2 < 4; tt2++){
            const int kb = 64*kg + 16*tt2;
            float sa[2][2][4];
#pragma unroll
            for (int rb = 0; rb < 2; rb++)
#pragma unroll
                for (int jj = 0; jj < 2; jj++)
#pragma unroll
                    for (int j = 0; j < 4; j++) sa[rb][jj][j] = 0.f;
#pragma unroll
            for (int jj = 0; jj < 2; jj++){
                int row = kb + 8*jj + l7;
#pragma unroll
                for (int c = 0; c < 4; c++){
                    uint32_t bv[4];
                    int chunk = 4*c + (lane >> 3);
                    ldsm_x4(bv, kbuf + row*256 + (uint32_t)((chunk ^ l7) << 4));
                    mma_bf16(sa[0][jj], qa[0][2*c],   bv);
                    mma_bf16(sa[0][jj], qa[0][2*c+1], bv + 2);
                    mma_bf16(sa[1][jj], qa[1][2*c],   bv);
                    mma_bf16(sa[1][jj], qa[1][2*c+1], bv + 2);
                }
            }
            uint32_t pa[2][4];
#pragma unroll
            for (int rb = 0; rb < 2; rb++){
                float e00 = ex2f(sa[rb][0][0]*C), e01 = ex2f(sa[rb][0][1]*C);
                float e02 = ex2f(sa[rb][0][2]*C), e03 = ex2f(sa[rb][0][3]*C);
                float e10 = ex2f(sa[rb][1][0]*C), e11 = ex2f(sa[rb][1][1]*C);
                float e12 = ex2f(sa[rb][1][2]*C), e13 = ex2f(sa[rb][1][3]*C);
                ls[rb][0] += e00 + e01 + e10 + e11;
                ls[rb][1] += e02 + e03 + e12 + e13;
                __nv_bfloat162 h;
                h = __floats2bfloat162_rn(e00, e01); pa[rb][0] = *(uint32_t*)&h;
                h = __floats2bfloat162_rn(e02, e03); pa[rb][1] = *(uint32_t*)&h;
                h = __floats2bfloat162_rn(e10, e11); pa[rb][2] = *(uint32_t*)&h;
                h = __floats2bfloat162_rn(e12, e13); pa[rb][3] = *(uint32_t*)&h;
            }
            int vrow = kb + l7 + ((lane >> 3) & 1) * 8;
#pragma unroll
            for (int u2 = 0; u2 < 8; u2++){
                uint32_t bv[4];
                int chunk = 2*u2 + (lane >> 4);
                ldsm_x4_t(bv, vbuf + vrow*256 + (uint32_t)((chunk ^ l7) << 4));
                mma_bf16(oa[0][2*u2],     pa[0], bv);
                mma_bf16(oa[0][2*u2 + 1], pa[0], bv + 2);
                mma_bf16(oa[1][2*u2],     pa[1], bv);
                mma_bf16(oa[1][2*u2 + 1], pa[1], bv + 2);
            }
        }
        if (i < 14){
            __syncthreads();
            load_kv(sb + (uint32_t)(i & 1)*65536, Kg, Vg, i + 2, t);
        }
    }

#pragma unroll
    for (int rb = 0; rb < 2; rb++)
#pragma unroll
        for (int j = 0; j < 2; j++){
            ls[rb][j] += __shfl_xor_sync(0xffffffffu, ls[rb][j], 1);
            ls[rb][j] += __shfl_xor_sync(0xffffffffu, ls[rb][j], 2);
        }

    // ---- combine key-group partials through smem ----
    float* smO = (float*)sm;
    float* smL = (float*)(sm + 128*ATT_OSTRIDE*4);
    uint32_t* stO = (uint32_t*)(sm + ATT_STAGE);
    __syncthreads();
    if (kg == 1){
#pragma unroll
        for (int rb = 0; rb < 2; rb++){
            int r0 = 32*qg + 16*rb + (lane >> 2);
            int c0 = 2*(lane & 3);
#pragma unroll
            for (int nt = 0; nt < 16; nt++){
                smO[r0*ATT_OSTRIDE + nt*8 + c0]           = oa[rb][nt][0];
                smO[r0*ATT_OSTRIDE + nt*8 + c0 + 1]       = oa[rb][nt][1];
                smO[(r0 + 8)*ATT_OSTRIDE + nt*8 + c0]     = oa[rb][nt][2];
                smO[(r0 + 8)*ATT_OSTRIDE + nt*8 + c0 + 1] = oa[rb][nt][3];
            }
            if ((lane & 3) == 0){
                smL[r0]     = ls[rb][0];
                smL[r0 + 8] = ls[rb][1];
            }
        }
    }
    __syncthreads();
    if (kg == 0){
#pragma unroll
        for (int rb = 0; rb < 2; rb++){
            int r0 = 32*qg + 16*rb + (lane >> 2);
            int c0 = 2*(lane & 3);
            float inv0 = 1.f / (ls[rb][0] + smL[r0]);
            float inv1 = 1.f / (ls[rb][1] + smL[r0 + 8]);
#pragma unroll
            for (int nt = 0; nt < 16; nt++){
                float o0 = (oa[rb][nt][0] + smO[r0*ATT_OSTRIDE + nt*8 + c0])           * inv0;
                float o1 = (oa[rb][nt][1] + smO[r0*ATT_OSTRIDE + nt*8 + c0 + 1])       * inv0;
                float o2 = (oa[rb][nt][2] + smO[(r0 + 8)*ATT_OSTRIDE + nt*8 + c0])     * inv1;
                float o3 = (oa[rb][nt][3] + smO[(r0 + 8)*ATT_OSTRIDE + nt*8 + c0 + 1]) * inv1;
                __nv_bfloat162 h0 = __floats2bfloat162_rn(o0, o1);
                __nv_bfloat162 h1 = __floats2bfloat162_rn(o2, o3);
                stO[r0*68 + 4*nt + (lane & 3)]       = *(uint32_t*)&h0;
                stO[(r0 + 8)*68 + 4*nt + (lane & 3)] = *(uint32_t*)&h1;
            }
        }
    }
    __syncthreads();
    // ---- coalesced copy-out (all 8 warps): 128 rows x 256B ----
    __nv_bfloat16* Obase = O + (size_t)(b*SS + qb*128)*UU;
#pragma unroll
    for (int p = 0; p < 8; p++){
        int row = (t >> 4) + p*16;
        int u4  = t & 15;
        uint4 v = *(uint4*)(stO + row*68 + u4*4);
        *(uint4*)(Obase + (size_t)row*UU + u4*8) = v;
    }
}

// ===========================================================================
extern "C" void kernel_launch(void* const* d_in, const int* in_sizes, int n_in,
                              void* d_out, int out_size)
{
    const float* X   = (const float*)d_in[0];
    const float* W_q = (const float*)d_in[1];
    const float* W_k = (const float*)d_in[2];
    const float* W_v = (const float*)d_in[3];
    const float* W_o = (const float*)d_in[4];
    const float* b_o = (const float*)d_in[5];
    float* out = (float*)d_out;

    __nv_bfloat16 *xb, *qb, *kb, *vb, *ob, *wq, *wk, *wv, *wo;
    cudaGetSymbolAddress((void**)&xb, g_Xb);
    cudaGetSymbolAddress((void**)&qb, g_Qb);
    cudaGetSymbolAddress((void**)&kb, g_Kb);
    cudaGetSymbolAddress((void**)&vb, g_Vb);
    cudaGetSymbolAddress((void**)&ob, g_Ob);
    cudaGetSymbolAddress((void**)&wq, g_Wq);
    cudaGetSymbolAddress((void**)&wk, g_Wk);
    cudaGetSymbolAddress((void**)&wv, g_Wv);
    cudaGetSymbolAddress((void**)&wo, g_Wo);

    cudaFuncSetAttribute(qkv_mma,  cudaFuncAttributeMaxDynamicSharedMemorySize, QKV_SMEM);
    cudaFuncSetAttribute(attn_mma, cudaFuncAttributeMaxDynamicSharedMemorySize, ATT_SMEM);
    cudaFuncSetAttribute(proj_mma, cudaFuncAttributeMaxDynamicSharedMemorySize, PROJ_SMEM);

    conv_all<<<(NX4 + 4*NW4 + 255)/256, 256>>>(X, W_q, W_k, W_v, W_o,
                                               xb, wq, wk, wv, wo);
    qkv_mma<<<dim3(MM/64, 3), 256, QKV_SMEM>>>(xb, wq, wk, wv, qb, kb, vb);
    attn_mma<<<dim3(SS/128, BB), 256, ATT_SMEM>>>(qb, kb, vb, ob);
    proj_mma<<<dim3(DD/128, MM/64), 256, PROJ_SMEM>>>(ob, wo, out, b_o, X);
}

// round 11
// speedup vs baseline: 1.2272x; 1.0074x over previous
#include <cuda_runtime.h>
#include <cuda_bf16.h>
#include <cstdint>

#define BB 8
#define SS 2048
#define DD 256
#define UU 128
#define MM (BB*SS)

// ---------------- device scratch (bf16 staging) ----------------
__device__ __nv_bfloat16 g_Qb[MM*UU];
__device__ __nv_bfloat16 g_Kb[MM*UU];
__device__ __nv_bfloat16 g_Vb[MM*UU];
__device__ __nv_bfloat16 g_Ob[MM*UU];
__device__ __nv_bfloat16 g_Wq[DD*UU], g_Wk[DD*UU], g_Wv[DD*UU];
__device__ __nv_bfloat16 g_Wo[UU*DD];

// ---------------- helpers ----------------
__device__ __forceinline__ uint32_t smem_u32(const void* p){
    uint32_t a;
    asm("{ .reg .u64 t; cvta.to.shared.u64 t, %1; cvt.u32.u64 %0, t; }":"=r"(a):"l"(p));
    return a;
}
__device__ __forceinline__ float ex2f(float x){
    float r; asm("ex2.approx.ftz.f32 %0, %1;":"=f"(r):"f"(x)); return r;
}
__device__ __forceinline__ void mma_bf16(float* c, const uint32_t* a, const uint32_t* b){
    asm volatile("mma.sync.aligned.m16n8k16.row.col.f32.bf16.bf16.f32 "
        "{%0,%1,%2,%3}, {%4,%5,%6,%7}, {%8,%9}, {%0,%1,%2,%3};"
        : "+f"(c[0]),"+f"(c[1]),"+f"(c[2]),"+f"(c[3])
        : "r"(a[0]),"r"(a[1]),"r"(a[2]),"r"(a[3]), "r"(b[0]),"r"(b[1]));
}
__device__ __forceinline__ void ldsm_x4(uint32_t* r, uint32_t addr){
    asm volatile("ldmatrix.sync.aligned.m8n8.x4.shared.b16 {%0,%1,%2,%3}, [%4];"
        : "=r"(r[0]),"=r"(r[1]),"=r"(r[2]),"=r"(r[3]) : "r"(addr));
}
__device__ __forceinline__ void ldsm_x4_t(uint32_t* r, uint32_t addr){
    asm volatile("ldmatrix.sync.aligned.m8n8.x4.trans.shared.b16 {%0,%1,%2,%3}, [%4];"
        : "=r"(r[0]),"=r"(r[1]),"=r"(r[2]),"=r"(r[3]) : "r"(addr));
}
#define CP16(dst, src) asm volatile("cp.async.cg.shared.global [%0], [%1], 16;" :: "r"(dst), "l"(src) : "memory")
#define CP_COMMIT()    asm volatile("cp.async.commit_group;" ::: "memory")
#define CP_WAIT0()     asm volatile("cp.async.wait_group 0;" ::: "memory")
#define CP_WAIT1()     asm volatile("cp.async.wait_group 1;" ::: "memory")

// ===========================================================================
// Weights fp32 -> bf16 convert (tiny launch; X conversion fused into qkv)
// ===========================================================================
#define NW4 (DD*UU/4)
__global__ void conv_w(const float* __restrict__ Wq, const float* __restrict__ Wk,
                       const float* __restrict__ Wv, const float* __restrict__ Wo,
                       __nv_bfloat16* __restrict__ wq, __nv_bfloat16* __restrict__ wk,
                       __nv_bfloat16* __restrict__ wv, __nv_bfloat16* __restrict__ wo)
{
    int i = blockIdx.x * blockDim.x + threadIdx.x;
    const float* src; __nv_bfloat16* dst; int j;
    if (i < NW4)              { src = Wq; dst = wq; j = i; }
    else if (i < 2*NW4)       { src = Wk; dst = wk; j = i - NW4; }
    else if (i < 3*NW4)       { src = Wv; dst = wv; j = i - 2*NW4; }
    else if (i < 4*NW4)       { src = Wo; dst = wo; j = i - 3*NW4; }
    else return;
    float4 v = ((const float4*)src)[j];
    __nv_bfloat162 a = __floats2bfloat162_rn(v.x, v.y);
    __nv_bfloat162 b = __floats2bfloat162_rn(v.z, v.w);
    uint2 o; o.x = *(uint32_t*)&a; o.y = *(uint32_t*)&b;
    ((uint2*)dst)[j] = o;
}

// ===========================================================================
// QKV projection: reads X fp32 directly (LDG + in-register bf16 convert + STS),
// W via cp.async double buffer. 64-row tiles, occ 3, staged coalesced epilogue.
// smem: X bf16 2x8KB @0, W 2x16KB @16384  (48KB)
// ===========================================================================
#define QKV_SMEM 49152
__global__ void __launch_bounds__(256, 3)
qkv_mma(const float* __restrict__ X,
        const __nv_bfloat16* __restrict__ Wqb, const __nv_bfloat16* __restrict__ Wkb,
        const __nv_bfloat16* __restrict__ Wvb,
        __nv_bfloat16* __restrict__ Qb, __nv_bfloat16* __restrict__ Kb,
        __nv_bfloat16* __restrict__ Vb)
{
    extern __shared__ __align__(128) char sm[];
    const uint32_t sb = smem_u32(sm);
    const int t = threadIdx.x, w = t >> 5, lane = t & 31, l7 = lane & 7;
    const int qg = w & 3, cg = w >> 2;
    const int z = blockIdx.y;
    const __nv_bfloat16* Wb = (z == 0) ? Wqb : (z == 1) ? Wkb : Wvb;
    __nv_bfloat16* Ob = (z == 0) ? Qb : (z == 1) ? Kb : Vb;
    const int rowBase = blockIdx.x * 64;
    const float* Xg = X + (size_t)rowBase * DD;
    const char* Wg = (const char*)Wb;

    // per-thread X prefetch registers (one 64x64 chunk = 4 float4/thread)
    float4 xr[4];
    const int xrow = t >> 4, xc4 = t & 15;   // row 0..15 base, float4 col 0..15
    auto ldg_x = [&](int kc){
#pragma unroll
        for (int q = 0; q < 4; q++)
            xr[q] = *(const float4*)(Xg + (size_t)(xrow + q*16)*DD + kc*64 + xc4*4);
    };
    auto sts_x = [&](int buf){             // buf MUST be 0 or 1
        char* xd = sm + buf*8192;
#pragma unroll
        for (int q = 0; q < 4; q++){
            int row = xrow + q*16;
            __nv_bfloat162 a = __floats2bfloat162_rn(xr[q].x, xr[q].y);
            __nv_bfloat162 b = __floats2bfloat162_rn(xr[q].z, xr[q].w);
            uint32_t off = (uint32_t)row*128u
                         + (uint32_t)((((xc4 >> 1)) ^ (row & 7)) << 4)
                         + (uint32_t)((xc4 & 1) * 8);
            uint2 v; v.x = *(uint32_t*)&a; v.y = *(uint32_t*)&b;
            *(uint2*)(xd + off) = v;
        }
    };
    auto load_w = [&](int kc, int buf){
        uint32_t wd = sb + 16384 + (uint32_t)buf * 16384;   // W: 64 x 128 bf16
#pragma unroll
        for (int q = 0; q < 4; q++){
            int idx = t + q*256, row = idx >> 4, ch = idx & 15;
            CP16(wd + row*256 + (uint32_t)((ch ^ (row & 7)) << 4),
                 Wg + (size_t)(kc*64 + row)*256 + ch*16);
        }
        CP_COMMIT();
    };

    float acc[8][4];
#pragma unroll
    for (int i = 0; i < 8; i++)
#pragma unroll
        for (int j = 0; j < 4; j++) acc[i][j] = 0.f;

    ldg_x(0);
    load_w(0, 0);
    load_w(1, 1);
    sts_x(0);
    ldg_x(1);

    for (int kc = 0; kc < 4; kc++){
        if (kc < 3) CP_WAIT1(); else CP_WAIT0();
        __syncthreads();
        const uint32_t xb = sb + (uint32_t)(kc & 1)*8192;
        const uint32_t wb = sb + 16384 + (uint32_t)(kc & 1)*16384;
#pragma unroll
        for (int t4 = 0; t4 < 4; t4++){
            uint32_t a[4];
            int arow = 16*qg + (lane & 15);
            int ach  = 2*t4 + (lane >> 4);
            ldsm_x4(a, xb + arow*128 + (uint32_t)((ach ^ (arow & 7)) << 4));
            int krow = 16*t4 + l7 + ((lane >> 3) & 1)*8;
#pragma unroll
            for (int u2 = 0; u2 < 4; u2++){
                uint32_t bv[4];
                int ch = 2*(4*cg + u2) + (lane >> 4);
                ldsm_x4_t(bv, wb + krow*256 + (uint32_t)((ch ^ l7) << 4));
                mma_bf16(acc[2*u2],     a, bv);
                mma_bf16(acc[2*u2 + 1], a, bv + 2);
            }
        }
        __syncthreads();
        if (kc < 3) sts_x((kc + 1) & 1);    // FIX: buffer index mod 2
        if (kc < 2){ ldg_x(kc + 2); load_w(kc + 2, kc & 1); }
    }

    // ---- staged coalesced epilogue: [64][68] u32 (bf16x2) ----
    __syncthreads();
    uint32_t* st = (uint32_t*)sm;
    {
        int r = 16*qg + (lane >> 2);
        int c2base = 32*cg + (lane & 3);
#pragma unroll
        for (int nt = 0; nt < 8; nt++){
            __nv_bfloat162 h0 = __floats2bfloat162_rn(acc[nt][0], acc[nt][1]);
            __nv_bfloat162 h1 = __floats2bfloat162_rn(acc[nt][2], acc[nt][3]);
            st[r*68 + c2base + 4*nt]       = *(uint32_t*)&h0;
            st[(r + 8)*68 + c2base + 4*nt] = *(uint32_t*)&h1;
        }
    }
    __syncthreads();
#pragma unroll
    for (int p = 0; p < 4; p++){
        int row = (t >> 4) + p*16;
        int u4  = t & 15;
        uint4 v = *(uint4*)(st + row*68 + u4*4);
        *(uint4*)(Ob + (size_t)(rowBase + row)*UU + u4*8) = v;
    }
}

// ===========================================================================
// Output projection: 64x128 tiles, occ 3, smem-staged coalesced epilogue.
// ===========================================================================
#define PROJ_SMEM 49152
__global__ void __launch_bounds__(256, 3)
proj_mma(const __nv_bfloat16* __restrict__ Ab, const __nv_bfloat16* __restrict__ Wob,
         float* __restrict__ C, const float* __restrict__ bias,
         const float* __restrict__ res)
{
    extern __shared__ __align__(128) char sm[];
    const uint32_t sb = smem_u32(sm);
    const int t = threadIdx.x, w = t >> 5, lane = t & 31, l7 = lane & 7;
    const int qg = w & 3, cg = w >> 2;
    const int rowBase = blockIdx.y * 64, colBase = blockIdx.x * 128;

    const char* Ag = (const char*)(Ab + (size_t)rowBase * UU);
    const char* Wg = (const char*)Wob + (size_t)colBase * 2;
#pragma unroll
    for (int q = 0; q < 4; q++){
        int idx = t + q*256, row = idx >> 4, ch = idx & 15;
        CP16(sb + row*256 + (uint32_t)((ch ^ (row & 7)) << 4),
             Ag + (size_t)row*256 + ch*16);
    }
#pragma unroll
    for (int q = 0; q < 8; q++){
        int idx = t + q*256, row = idx >> 4, ch = idx & 15;
        CP16(sb + 16384 + row*256 + (uint32_t)((ch ^ (row & 7)) << 4),
             Wg + (size_t)row*512 + ch*16);
    }
    CP_COMMIT();
    CP_WAIT0();
    __syncthreads();

    float acc[8][4];
#pragma unroll
    for (int i = 0; i < 8; i++)
#pragma unroll
        for (int j = 0; j < 4; j++) acc[i][j] = 0.f;

#pragma unroll
    for (int t4 = 0; t4 < 8; t4++){
        uint32_t a[4];
        int arow = 16*qg + (lane & 15);
        int ach  = 2*t4 + (lane >> 4);
        ldsm_x4(a, sb + arow*256 + (uint32_t)((ach ^ (arow & 7)) << 4));
        int krow = 16*t4 + l7 + ((lane >> 3) & 1)*8;
#pragma unroll
        for (int u2 = 0; u2 < 4; u2++){
            uint32_t bv[4];
            int ch = 2*(4*cg + u2) + (lane >> 4);
            ldsm_x4_t(bv, sb + 16384 + krow*256 + (uint32_t)((ch ^ l7) << 4));
            mma_bf16(acc[2*u2],     a, bv);
            mma_bf16(acc[2*u2 + 1], a, bv + 2);
        }
    }

    // ---- staged coalesced epilogue: [64][132] fp32 ----
    __syncthreads();
    float* st = (float*)sm;
    {
        int r = 16*qg + (lane >> 2);
        int cb = 64*cg + 2*(lane & 3);
#pragma unroll
        for (int nt = 0; nt < 8; nt++){
            int c = cb + 8*nt;
            st[r*132 + c]           = acc[nt][0];
            st[r*132 + c + 1]       = acc[nt][1];
            st[(r + 8)*132 + c]     = acc[nt][2];
            st[(r + 8)*132 + c + 1] = acc[nt][3];
        }
    }
    __syncthreads();
#pragma unroll
    for (int p = 0; p < 8; p++){
        int row = (t >> 5) + p*8;
        int c4  = t & 31;
        float4 v  = *(float4*)(st + row*132 + c4*4);
        float4 bi = *(const float4*)(bias + colBase + c4*4);
        float4 rs = *(const float4*)(res + (size_t)(rowBase + row)*DD + colBase + c4*4);
        v.x += bi.x + rs.x; v.y += bi.y + rs.y;
        v.z += bi.z + rs.z; v.w += bi.w + rs.w;
        *(float4*)(C + (size_t)(rowBase + row)*DD + colBase + c4*4) = v;
    }
}

// ===========================================================================
// Flash attention, m32 warp tile + key-split, 128-key tiles, staged O output.
// ===========================================================================
#define ATT_OSTRIDE 136
#define ATT_STAGE   73728
#define ATT_SMEM   131072

__device__ __forceinline__ void load_kv(uint32_t dst, const char* Kg, const char* Vg,
                                        int tile, int t){
    const char* ks = Kg + (size_t)tile * 128 * 256;
    const char* vs = Vg + (size_t)tile * 128 * 256;
#pragma unroll
    for (int q = 0; q < 8; q++){
        int idx = t + q*256;
        int row = idx >> 4, ch = idx & 15;
        uint32_t d = dst + row*256 + (uint32_t)((ch ^ (row & 7)) << 4);
        CP16(d,         ks + (size_t)row*256 + ch*16);
        CP16(d + 32768, vs + (size_t)row*256 + ch*16);
    }
    CP_COMMIT();
}

__global__ void __launch_bounds__(256, 1)
attn_mma(const __nv_bfloat16* __restrict__ Q, const __nv_bfloat16* __restrict__ K,
         const __nv_bfloat16* __restrict__ V, __nv_bfloat16* __restrict__ O)
{
    extern __shared__ __align__(128) char sm[];
    const uint32_t sb = smem_u32(sm);
    const int t = threadIdx.x, w = t >> 5, lane = t & 31, l7 = lane & 7;
    const int qg = w & 3, kg = w >> 2;
    const int b = blockIdx.y, qb = blockIdx.x;

    const char* Qg = (const char*)(Q + (size_t)(b*SS + qb*128)*UU);
#pragma unroll
    for (int q = 0; q < 8; q++){
        int idx = t + q*256;
        int row = idx >> 4, ch = idx & 15;
        CP16(sb + row*256 + (uint32_t)((ch ^ (row & 7)) << 4),
             Qg + (size_t)row*256 + ch*16);
    }
    CP_COMMIT();
    CP_WAIT0();
    __syncthreads();

    uint32_t qa[2][8][4];
#pragma unroll
    for (int rb = 0; rb < 2; rb++){
        int row = 32*qg + 16*rb + (lane & 15);
        int rx  = row & 7;
        int cb  = (lane >> 4) & 1;
#pragma unroll
        for (int kt = 0; kt < 8; kt++){
            int chunk = 2*kt + cb;
            ldsm_x4(qa[rb][kt], sb + row*256 + (uint32_t)((chunk ^ rx) << 4));
        }
    }
    __syncthreads();

    float oa[2][16][4];
#pragma unroll
    for (int rb = 0; rb < 2; rb++)
#pragma unroll
        for (int i = 0; i < 16; i++)
#pragma unroll
            for (int j = 0; j < 4; j++) oa[rb][i][j] = 0.f;
    float ls[2][2] = {{0.f,0.f},{0.f,0.f}};

    const char* Kg = (const char*)(K + (size_t)(b*SS)*UU);
    const char* Vg = (const char*)(V + (size_t)(b*SS)*UU);

    load_kv(sb,         Kg, Vg, 0, t);
    load_kv(sb + 65536, Kg, Vg, 1, t);

    const float C = 0.12751751699104088f;   // log2(e) / sqrt(128)

    for (int i = 0; i < 16; i++){
        if (i < 15) CP_WAIT1(); else CP_WAIT0();
        __syncthreads();
        const uint32_t kbuf = sb + (uint32_t)(i & 1)*65536;
        const uint32_t vbuf = kbuf + 32768;

#pragma unroll
        for (int tt2 = 0; tt2 < 4; tt2++){
            const int kb = 64*kg + 16*tt2;
            float sa[2][2][4];
#pragma unroll
            for (int rb = 0; rb < 2; rb++)
#pragma unroll
                for (int jj = 0; jj < 2; jj++)
#pragma unroll
                    for (int j = 0; j < 4; j++) sa[rb][jj][j] = 0.f;
#pragma unroll
            for (int jj = 0; jj < 2; jj++){
                int row = kb + 8*jj + l7;
#pragma unroll
                for (int c = 0; c < 4; c++){
                    uint32_t bv[4];
                    int chunk = 4*c + (lane >> 3);
                    ldsm_x4(bv, kbuf + row*256 + (uint32_t)((chunk ^ l7) << 4));
                    mma_bf16(sa[0][jj], qa[0][2*c],   bv);
                    mma_bf16(sa[0][jj], qa[0][2*c+1], bv + 2);
                    mma_bf16(sa[1][jj], qa[1][2*c],   bv);
                    mma_bf16(sa[1][jj], qa[1][2*c+1], bv + 2);
                }
            }
            uint32_t pa[2][4];
#pragma unroll
            for (int rb = 0; rb < 2; rb++){
                float e00 = ex2f(sa[rb][0][0]*C), e01 = ex2f(sa[rb][0][1]*C);
                float e02 = ex2f(sa[rb][0][2]*C), e03 = ex2f(sa[rb][0][3]*C);
                float e10 = ex2f(sa[rb][1][0]*C), e11 = ex2f(sa[rb][1][1]*C);
                float e12 = ex2f(sa[rb][1][2]*C), e13 = ex2f(sa[rb][1][3]*C);
                ls[rb][0] += e00 + e01 + e10 + e11;
                ls[rb][1] += e02 + e03 + e12 + e13;
                __nv_bfloat162 h;
                h = __floats2bfloat162_rn(e00, e01); pa[rb][0] = *(uint32_t*)&h;
                h = __floats2bfloat162_rn(e02, e03); pa[rb][1] = *(uint32_t*)&h;
                h = __floats2bfloat162_rn(e10, e11); pa[rb][2] = *(uint32_t*)&h;
                h = __floats2bfloat162_rn(e12, e13); pa[rb][3] = *(uint32_t*)&h;
            }
            int vrow = kb + l7 + ((lane >> 3) & 1) * 8;
#pragma unroll
            for (int u2 = 0; u2 < 8; u2++){
                uint32_t bv[4];
                int chunk = 2*u2 + (lane >> 4);
                ldsm_x4_t(bv, vbuf + vrow*256 + (uint32_t)((chunk ^ l7) << 4));
                mma_bf16(oa[0][2*u2],     pa[0], bv);
                mma_bf16(oa[0][2*u2 + 1], pa[0], bv + 2);
                mma_bf16(oa[1][2*u2],     pa[1], bv);
                mma_bf16(oa[1][2*u2 + 1], pa[1], bv + 2);
            }
        }
        if (i < 14){
            __syncthreads();
            load_kv(sb + (uint32_t)(i & 1)*65536, Kg, Vg, i + 2, t);
        }
    }

#pragma unroll
    for (int rb = 0; rb < 2; rb++)
#pragma unroll
        for (int j = 0; j < 2; j++){
            ls[rb][j] += __shfl_xor_sync(0xffffffffu, ls[rb][j], 1);
            ls[rb][j] += __shfl_xor_sync(0xffffffffu, ls[rb][j], 2);
        }

    // ---- combine key-group partials through smem ----
    float* smO = (float*)sm;
    float* smL = (float*)(sm + 128*ATT_OSTRIDE*4);
    uint32_t* stO = (uint32_t*)(sm + ATT_STAGE);
    __syncthreads();
    if (kg == 1){
#pragma unroll
        for (int rb = 0; rb < 2; rb++){
            int r0 = 32*qg + 16*rb + (lane >> 2);
            int c0 = 2*(lane & 3);
#pragma unroll
            for (int nt = 0; nt < 16; nt++){
                smO[r0*ATT_OSTRIDE + nt*8 + c0]           = oa[rb][nt][0];
                smO[r0*ATT_OSTRIDE + nt*8 + c0 + 1]       = oa[rb][nt][1];
                smO[(r0 + 8)*ATT_OSTRIDE + nt*8 + c0]     = oa[rb][nt][2];
                smO[(r0 + 8)*ATT_OSTRIDE + nt*8 + c0 + 1] = oa[rb][nt][3];
            }
            if ((lane & 3) == 0){
                smL[r0]     = ls[rb][0];
                smL[r0 + 8] = ls[rb][1];
            }
        }
    }
    __syncthreads();
    if (kg == 0){
#pragma unroll
        for (int rb = 0; rb < 2; rb++){
            int r0 = 32*qg + 16*rb + (lane >> 2);
            int c0 = 2*(lane & 3);
            float inv0 = 1.f / (ls[rb][0] + smL[r0]);
            float inv1 = 1.f / (ls[rb][1] + smL[r0 + 8]);
#pragma unroll
            for (int nt = 0; nt < 16; nt++){
                float o0 = (oa[rb][nt][0] + smO[r0*ATT_OSTRIDE + nt*8 + c0])           * inv0;
                float o1 = (oa[rb][nt][1] + smO[r0*ATT_OSTRIDE + nt*8 + c0 + 1])       * inv0;
                float o2 = (oa[rb][nt][2] + smO[(r0 + 8)*ATT_OSTRIDE + nt*8 + c0])     * inv1;
                float o3 = (oa[rb][nt][3] + smO[(r0 + 8)*ATT_OSTRIDE + nt*8 + c0 + 1]) * inv1;
                __nv_bfloat162 h0 = __floats2bfloat162_rn(o0, o1);
                __nv_bfloat162 h1 = __floats2bfloat162_rn(o2, o3);
                stO[r0*68 + 4*nt + (lane & 3)]       = *(uint32_t*)&h0;
                stO[(r0 + 8)*68 + 4*nt + (lane & 3)] = *(uint32_t*)&h1;
            }
        }
    }
    __syncthreads();
    __nv_bfloat16* Obase = O + (size_t)(b*SS + qb*128)*UU;
#pragma unroll
    for (int p = 0; p < 8; p++){
        int row = (t >> 4) + p*16;
        int u4  = t & 15;
        uint4 v = *(uint4*)(stO + row*68 + u4*4);
        *(uint4*)(Obase + (size_t)row*UU + u4*8) = v;
    }
}

// ===========================================================================
extern "C" void kernel_launch(void* const* d_in, const int* in_sizes, int n_in,
                              void* d_out, int out_size)
{
    const float* X   = (const float*)d_in[0];
    const float* W_q = (const float*)d_in[1];
    const float* W_k = (const float*)d_in[2];
    const float* W_v = (const float*)d_in[3];
    const float* W_o = (const float*)d_in[4];
    const float* b_o = (const float*)d_in[5];
    float* out = (float*)d_out;

    __nv_bfloat16 *qb, *kb, *vb, *ob, *wq, *wk, *wv, *wo;
    cudaGetSymbolAddress((void**)&qb, g_Qb);
    cudaGetSymbolAddress((void**)&kb, g_Kb);
    cudaGetSymbolAddress((void**)&vb, g_Vb);
    cudaGetSymbolAddress((void**)&ob, g_Ob);
    cudaGetSymbolAddress((void**)&wq, g_Wq);
    cudaGetSymbolAddress((void**)&wk, g_Wk);
    cudaGetSymbolAddress((void**)&wv, g_Wv);
    cudaGetSymbolAddress((void**)&wo, g_Wo);

    cudaFuncSetAttribute(qkv_mma,  cudaFuncAttributeMaxDynamicSharedMemorySize, QKV_SMEM);
    cudaFuncSetAttribute(attn_mma, cudaFuncAttributeMaxDynamicSharedMemorySize, ATT_SMEM);
    cudaFuncSetAttribute(proj_mma, cudaFuncAttributeMaxDynamicSharedMemorySize, PROJ_SMEM);

    conv_w<<<(4*NW4 + 255)/256, 256>>>(W_q, W_k, W_v, W_o, wq, wk, wv, wo);
    qkv_mma<<<dim3(MM/64, 3), 256, QKV_SMEM>>>(X, wq, wk, wv, qb, kb, vb);
    attn_mma<<<dim3(SS/128, BB), 256, ATT_SMEM>>>(qb, kb, vb, ob);
    proj_mma<<<dim3(DD/128, MM/64), 256, PROJ_SMEM>>>(ob, wo, out, b_o, X);
}